// round 2
// baseline (speedup 1.0000x reference)
#include <cuda_runtime.h>

#define T     4096
#define C     1024
#define NF    256
#define N3    768          // 3 * NF
#define SCALE 0.0625f      // 1/sqrt(256)

// Scratch (alloc-free rule: __device__ globals)
__device__ float g_qkv[T * N3];            // 12 MB: [q | k | v] per row
__device__ float g_att[(size_t)T * T];     // 64 MB: scores -> probabilities

// ---------------------------------------------------------------------------
// Pass 1: qkv = x @ W + b     (M=4096, N=768, K=1024)
// 128x128 tile, BK=8, 256 threads, 8x8 per-thread microtile.
// ---------------------------------------------------------------------------
__global__ __launch_bounds__(256) void k_qkv(const float* __restrict__ x,
                                             const float* __restrict__ W,
                                             const float* __restrict__ bias) {
    __shared__ float As[8][128];
    __shared__ float Bs[8][128];
    const int tid = threadIdx.x;
    const int bm = blockIdx.y * 128;
    const int bn = blockIdx.x * 128;
    const int arow = tid >> 1, acol = (tid & 1) * 4;   // A: 128x8 tile, transpose-store
    const int brow = tid >> 5, bcol = (tid & 31) * 4;  // B: 8x128 tile, direct
    const int ty = tid >> 4, tx = tid & 15;

    float acc[8][8];
#pragma unroll
    for (int r = 0; r < 8; r++)
#pragma unroll
        for (int c = 0; c < 8; c++) acc[r][c] = 0.f;

    for (int k0 = 0; k0 < C; k0 += 8) {
        float4 av = *(const float4*)&x[(bm + arow) * C + k0 + acol];
        As[acol + 0][arow] = av.x;
        As[acol + 1][arow] = av.y;
        As[acol + 2][arow] = av.z;
        As[acol + 3][arow] = av.w;
        *(float4*)&Bs[brow][bcol] = *(const float4*)&W[(k0 + brow) * N3 + bn + bcol];
        __syncthreads();
#pragma unroll
        for (int kk = 0; kk < 8; kk++) {
            float a[8], b[8];
            *(float4*)&a[0] = *(float4*)&As[kk][ty * 8];
            *(float4*)&a[4] = *(float4*)&As[kk][ty * 8 + 4];
            *(float4*)&b[0] = *(float4*)&Bs[kk][tx * 8];
            *(float4*)&b[4] = *(float4*)&Bs[kk][tx * 8 + 4];
#pragma unroll
            for (int r = 0; r < 8; r++)
#pragma unroll
                for (int c = 0; c < 8; c++) acc[r][c] += a[r] * b[c];
        }
        __syncthreads();
    }
#pragma unroll
    for (int r = 0; r < 8; r++) {
        const int row = bm + ty * 8 + r;
#pragma unroll
        for (int cc = 0; cc < 8; cc += 4) {
            const int col = bn + tx * 8 + cc;
            float4 o;
            o.x = acc[r][cc + 0] + bias[col + 0];
            o.y = acc[r][cc + 1] + bias[col + 1];
            o.z = acc[r][cc + 2] + bias[col + 2];
            o.w = acc[r][cc + 3] + bias[col + 3];
            *(float4*)&g_qkv[row * N3 + col] = o;
        }
    }
}

// ---------------------------------------------------------------------------
// Pass 2: att[i][j] = mask ? (q_i . k_j) * SCALE : 0
// 128x128 tile over (i, j), K = NF = 256. Masked entries -> 0.0 so that
// softmax (which only reads [n_padd, i]) and p@v (which reads full tiles)
// are both exact.
// ---------------------------------------------------------------------------
__global__ __launch_bounds__(256) void k_scores(const int* __restrict__ npadd_p) {
    const int n_padd = *npadd_p;
    const int bm = blockIdx.y * 128;  // i block
    const int bn = blockIdx.x * 128;  // j block
    if (bn > bm + 127) return;        // strictly above diagonal: never read later

    const int tid = threadIdx.x;
    const int ty = tid >> 4, tx = tid & 15;

    // Fully-masked tiles: zero-fill, skip GEMM
    if (bn + 127 < n_padd || bm + 127 < n_padd) {
#pragma unroll
        for (int r = 0; r < 8; r++) {
            const int i = bm + ty * 8 + r;
#pragma unroll
            for (int c = 0; c < 8; c++) g_att[(size_t)i * T + bn + tx * 8 + c] = 0.f;
        }
        return;
    }

    __shared__ float As[8][128];
    __shared__ float Bs[8][128];
    const int arow = tid >> 1, acol = (tid & 1) * 4;

    float acc[8][8];
#pragma unroll
    for (int r = 0; r < 8; r++)
#pragma unroll
        for (int c = 0; c < 8; c++) acc[r][c] = 0.f;

    for (int k0 = 0; k0 < NF; k0 += 8) {
        float4 av = *(const float4*)&g_qkv[(bm + arow) * N3 + k0 + acol];        // q
        As[acol + 0][arow] = av.x;
        As[acol + 1][arow] = av.y;
        As[acol + 2][arow] = av.z;
        As[acol + 3][arow] = av.w;
        float4 bv = *(const float4*)&g_qkv[(bn + arow) * N3 + NF + k0 + acol];   // k
        Bs[acol + 0][arow] = bv.x;
        Bs[acol + 1][arow] = bv.y;
        Bs[acol + 2][arow] = bv.z;
        Bs[acol + 3][arow] = bv.w;
        __syncthreads();
#pragma unroll
        for (int kk = 0; kk < 8; kk++) {
            float a[8], b[8];
            *(float4*)&a[0] = *(float4*)&As[kk][ty * 8];
            *(float4*)&a[4] = *(float4*)&As[kk][ty * 8 + 4];
            *(float4*)&b[0] = *(float4*)&Bs[kk][tx * 8];
            *(float4*)&b[4] = *(float4*)&Bs[kk][tx * 8 + 4];
#pragma unroll
            for (int r = 0; r < 8; r++)
#pragma unroll
                for (int c = 0; c < 8; c++) acc[r][c] += a[r] * b[c];
        }
        __syncthreads();
    }
#pragma unroll
    for (int r = 0; r < 8; r++) {
        const int i = bm + ty * 8 + r;
#pragma unroll
        for (int c = 0; c < 8; c++) {
            const int j = bn + tx * 8 + c;
            const float v = (j <= i && j >= n_padd) ? acc[r][c] * SCALE : 0.f;
            g_att[(size_t)i * T + j] = v;
        }
    }
}

// ---------------------------------------------------------------------------
// Pass 3: row softmax over att[i][n_padd .. i], staged in SMEM.
// Warp-shuffle reductions + 8-slot SMEM combine.
// ---------------------------------------------------------------------------
__global__ __launch_bounds__(256) void k_softmax(const int* __restrict__ npadd_p) {
    const int n_padd = *npadd_p;
    const int i = blockIdx.x;
    if (i < n_padd) return;
    const int L = i - n_padd + 1;

    __shared__ float row[T];
    __shared__ float red[8];
    float* att = &g_att[(size_t)i * T + n_padd];
    const int tid = threadIdx.x;
    const int lane = tid & 31, wid = tid >> 5;

    float m = -3.4e38f;
    for (int j = tid; j < L; j += 256) {
        const float v = att[j];
        row[j] = v;
        m = fmaxf(m, v);
    }
#pragma unroll
    for (int s = 16; s > 0; s >>= 1) m = fmaxf(m, __shfl_xor_sync(0xffffffffu, m, s));
    if (lane == 0) red[wid] = m;
    __syncthreads();
    m = red[0];
#pragma unroll
    for (int w = 1; w < 8; w++) m = fmaxf(m, red[w]);
    __syncthreads();

    float sum = 0.f;
    for (int j = tid; j < L; j += 256) {
        const float e = __expf(row[j] - m);
        row[j] = e;
        sum += e;
    }
#pragma unroll
    for (int s = 16; s > 0; s >>= 1) sum += __shfl_xor_sync(0xffffffffu, sum, s);
    if (lane == 0) red[wid] = sum;
    __syncthreads();
    sum = red[0];
#pragma unroll
    for (int w = 1; w < 8; w++) sum += red[w];

    const float inv = 1.f / sum;
    for (int j = tid; j < L; j += 256) att[j] = row[j] * inv;
}

// ---------------------------------------------------------------------------
// Pass 4: y = p @ v     (M=4096, N=256, K in [16-aligned n_padd, row_block_end))
// 64x64 tile, BK=16, 256 threads, 4x4 microtile. Empty k-loop => zeros
// (covers i < n_padd rows exactly as the reference requires).
// ---------------------------------------------------------------------------
__global__ __launch_bounds__(256) void k_out(const int* __restrict__ npadd_p,
                                             float* __restrict__ out) {
    const int n_padd = *npadd_p;
    const int bm = blockIdx.y * 64;
    const int bn = blockIdx.x * 64;

    __shared__ float As[16][64];
    __shared__ float Bs[16][64];
    const int tid = threadIdx.x;
    const int arow = tid >> 2, acol = (tid & 3) * 4;   // A: 64x16 tile, transpose-store
    const int brow = tid >> 4, bcol = (tid & 15) * 4;  // B: 16x64 tile, direct
    const int ty = tid >> 4, tx = tid & 15;

    float acc[4][4];
#pragma unroll
    for (int r = 0; r < 4; r++)
#pragma unroll
        for (int c = 0; c < 4; c++) acc[r][c] = 0.f;

    const int kstart = (n_padd / 16) * 16;
    const int kend = bm + 64;  // only j <= max row index of this block matter

    for (int k0 = kstart; k0 < kend; k0 += 16) {
        float4 av = *(const float4*)&g_att[(size_t)(bm + arow) * T + k0 + acol];
        As[acol + 0][arow] = av.x;
        As[acol + 1][arow] = av.y;
        As[acol + 2][arow] = av.z;
        As[acol + 3][arow] = av.w;
        *(float4*)&Bs[brow][bcol] =
            *(const float4*)&g_qkv[(k0 + brow) * N3 + 2 * NF + bn + bcol];  // v
        __syncthreads();
#pragma unroll
        for (int kk = 0; kk < 16; kk++) {
            float4 a = *(float4*)&As[kk][ty * 4];
            float4 b = *(float4*)&Bs[kk][tx * 4];
            acc[0][0] += a.x * b.x; acc[0][1] += a.x * b.y; acc[0][2] += a.x * b.z; acc[0][3] += a.x * b.w;
            acc[1][0] += a.y * b.x; acc[1][1] += a.y * b.y; acc[1][2] += a.y * b.z; acc[1][3] += a.y * b.w;
            acc[2][0] += a.z * b.x; acc[2][1] += a.z * b.y; acc[2][2] += a.z * b.z; acc[2][3] += a.z * b.w;
            acc[3][0] += a.w * b.x; acc[3][1] += a.w * b.y; acc[3][2] += a.w * b.z; acc[3][3] += a.w * b.w;
        }
        __syncthreads();
    }
#pragma unroll
    for (int r = 0; r < 4; r++) {
        const int row = bm + ty * 4 + r;
        float4 o;
        o.x = acc[r][0]; o.y = acc[r][1]; o.z = acc[r][2]; o.w = acc[r][3];
        *(float4*)&out[row * NF + bn + tx * 4] = o;
    }
}

// ---------------------------------------------------------------------------
extern "C" void kernel_launch(void* const* d_in, const int* in_sizes, int n_in,
                              void* d_out, int out_size) {
    const float* x = (const float*)d_in[0];
    const float* W = (const float*)d_in[1];
    const float* b = (const float*)d_in[2];
    const int* n_padd = (const int*)d_in[3];
    float* out = (float*)d_out;

    k_qkv<<<dim3(N3 / 128, T / 128), 256>>>(x, W, b);
    k_scores<<<dim3(T / 128, T / 128), 256>>>(n_padd);
    k_softmax<<<T, 256>>>(n_padd);
    k_out<<<dim3(NF / 64, T / 64), 256>>>(n_padd, out);
}

// round 4
// speedup vs baseline: 1.4372x; 1.4372x over previous
#include <cuda_runtime.h>

#define T     4096
#define C     1024
#define NF    256
#define N3    768          // 3 * NF
#define SCALE 0.0625f      // 1/sqrt(256)
#define KSPLIT 8
#define CH    (T / KSPLIT) // 512

// Scratch (alloc-free rule: __device__ globals)
__device__ float g_qkv[T * N3];                        // 12 MB: [q | k | v]
__device__ float g_att[(size_t)T * T];                 // 64 MB: scores -> probs
__device__ float g_part[(size_t)KSPLIT * T * NF];      // 32 MB: split-K partials

// ---------------------------------------------------------------------------
// Pass 1: qkv = x @ W + b    (M=4096, N=768, K=1024)
// 128x64 tile, BK=16, 128 threads, 8x8 microtile. Grid 12x32 = 384 blocks.
// ---------------------------------------------------------------------------
__global__ __launch_bounds__(128) void k_qkv(const float* __restrict__ x,
                                             const float* __restrict__ W,
                                             const float* __restrict__ bias) {
    __shared__ float As[16][132];   // +4 pad: kill transpose-store bank conflicts
    __shared__ float Bs[16][68];
    const int tid = threadIdx.x;
    const int bm = blockIdx.y * 128;
    const int bn = blockIdx.x * 64;
    const int ar = tid >> 2, ac = (tid & 3) * 4;   // A loads: 4 rows strided by 32
    const int br = tid >> 3, bc = (tid & 7) * 8;   // B loads: 2 float4
    const int ty = tid >> 3, tx = tid & 7;

    float acc[8][8];
#pragma unroll
    for (int r = 0; r < 8; r++)
#pragma unroll
        for (int c = 0; c < 8; c++) acc[r][c] = 0.f;

    for (int k0 = 0; k0 < C; k0 += 16) {
#pragma unroll
        for (int l = 0; l < 4; l++) {
            const int row = ar + 32 * l;
            float4 av = *(const float4*)&x[(bm + row) * C + k0 + ac];
            As[ac + 0][row] = av.x;
            As[ac + 1][row] = av.y;
            As[ac + 2][row] = av.z;
            As[ac + 3][row] = av.w;
        }
        *(float4*)&Bs[br][bc]     = *(const float4*)&W[(k0 + br) * N3 + bn + bc];
        *(float4*)&Bs[br][bc + 4] = *(const float4*)&W[(k0 + br) * N3 + bn + bc + 4];
        __syncthreads();
#pragma unroll
        for (int kk = 0; kk < 16; kk++) {
            float a[8], b[8];
            *(float4*)&a[0] = *(float4*)&As[kk][ty * 8];
            *(float4*)&a[4] = *(float4*)&As[kk][ty * 8 + 4];
            *(float4*)&b[0] = *(float4*)&Bs[kk][tx * 8];
            *(float4*)&b[4] = *(float4*)&Bs[kk][tx * 8 + 4];
#pragma unroll
            for (int r = 0; r < 8; r++)
#pragma unroll
                for (int c = 0; c < 8; c++) acc[r][c] += a[r] * b[c];
        }
        __syncthreads();
    }
#pragma unroll
    for (int r = 0; r < 8; r++) {
        const int row = bm + ty * 8 + r;
#pragma unroll
        for (int cc = 0; cc < 8; cc += 4) {
            const int col = bn + tx * 8 + cc;
            float4 o;
            o.x = acc[r][cc + 0] + bias[col + 0];
            o.y = acc[r][cc + 1] + bias[col + 1];
            o.z = acc[r][cc + 2] + bias[col + 2];
            o.w = acc[r][cc + 3] + bias[col + 3];
            *(float4*)&g_qkv[row * N3 + col] = o;
        }
    }
}

// ---------------------------------------------------------------------------
// Pass 2: att[i][j] = mask ? (q_i . k_j) * SCALE : 0
// ---------------------------------------------------------------------------
__global__ __launch_bounds__(256) void k_scores(const int* __restrict__ npadd_p) {
    const int n_padd = *npadd_p;
    const int bm = blockIdx.y * 128;
    const int bn = blockIdx.x * 128;
    if (bn > bm + 127) return;

    const int tid = threadIdx.x;
    const int ty = tid >> 4, tx = tid & 15;

    if (bn + 127 < n_padd || bm + 127 < n_padd) {
#pragma unroll
        for (int r = 0; r < 8; r++) {
            const int i = bm + ty * 8 + r;
#pragma unroll
            for (int c = 0; c < 8; c++) g_att[(size_t)i * T + bn + tx * 8 + c] = 0.f;
        }
        return;
    }

    __shared__ float As[8][132];
    __shared__ float Bs[8][132];
    const int arow = tid >> 1, acol = (tid & 1) * 4;

    float acc[8][8];
#pragma unroll
    for (int r = 0; r < 8; r++)
#pragma unroll
        for (int c = 0; c < 8; c++) acc[r][c] = 0.f;

    for (int k0 = 0; k0 < NF; k0 += 8) {
        float4 av = *(const float4*)&g_qkv[(bm + arow) * N3 + k0 + acol];        // q
        As[acol + 0][arow] = av.x;
        As[acol + 1][arow] = av.y;
        As[acol + 2][arow] = av.z;
        As[acol + 3][arow] = av.w;
        float4 bv = *(const float4*)&g_qkv[(bn + arow) * N3 + NF + k0 + acol];   // k
        Bs[acol + 0][arow] = bv.x;
        Bs[acol + 1][arow] = bv.y;
        Bs[acol + 2][arow] = bv.z;
        Bs[acol + 3][arow] = bv.w;
        __syncthreads();
#pragma unroll
        for (int kk = 0; kk < 8; kk++) {
            float a[8], b[8];
            *(float4*)&a[0] = *(float4*)&As[kk][ty * 8];
            *(float4*)&a[4] = *(float4*)&As[kk][ty * 8 + 4];
            *(float4*)&b[0] = *(float4*)&Bs[kk][tx * 8];
            *(float4*)&b[4] = *(float4*)&Bs[kk][tx * 8 + 4];
#pragma unroll
            for (int r = 0; r < 8; r++)
#pragma unroll
                for (int c = 0; c < 8; c++) acc[r][c] += a[r] * b[c];
        }
        __syncthreads();
    }
#pragma unroll
    for (int r = 0; r < 8; r++) {
        const int i = bm + ty * 8 + r;
#pragma unroll
        for (int c = 0; c < 8; c++) {
            const int j = bn + tx * 8 + c;
            const float v = (j <= i && j >= n_padd) ? acc[r][c] * SCALE : 0.f;
            g_att[(size_t)i * T + j] = v;
        }
    }
}

// ---------------------------------------------------------------------------
// Pass 3: row softmax over att[i][n_padd .. i]
// ---------------------------------------------------------------------------
__global__ __launch_bounds__(256) void k_softmax(const int* __restrict__ npadd_p) {
    const int n_padd = *npadd_p;
    const int i = blockIdx.x;
    if (i < n_padd) return;
    const int L = i - n_padd + 1;

    __shared__ float row[T];
    __shared__ float red[8];
    float* att = &g_att[(size_t)i * T + n_padd];
    const int tid = threadIdx.x;
    const int lane = tid & 31, wid = tid >> 5;

    float m = -3.4e38f;
    for (int j = tid; j < L; j += 256) {
        const float v = att[j];
        row[j] = v;
        m = fmaxf(m, v);
    }
#pragma unroll
    for (int s = 16; s > 0; s >>= 1) m = fmaxf(m, __shfl_xor_sync(0xffffffffu, m, s));
    if (lane == 0) red[wid] = m;
    __syncthreads();
    m = red[0];
#pragma unroll
    for (int w = 1; w < 8; w++) m = fmaxf(m, red[w]);
    __syncthreads();

    float sum = 0.f;
    for (int j = tid; j < L; j += 256) {
        const float e = __expf(row[j] - m);
        row[j] = e;
        sum += e;
    }
#pragma unroll
    for (int s = 16; s > 0; s >>= 1) sum += __shfl_xor_sync(0xffffffffu, sum, s);
    if (lane == 0) red[wid] = sum;
    __syncthreads();
    sum = red[0];
#pragma unroll
    for (int w = 1; w < 8; w++) sum += red[w];

    const float inv = 1.f / sum;
    for (int j = tid; j < L; j += 256) att[j] = row[j] * inv;
}

// ---------------------------------------------------------------------------
// Pass 4a: split-K partials of y = p @ v
// Grid (NF/64, T/128, KSPLIT). 128x64 tile, BK=16, 128 thr, 8x8 microtile.
// Chunk s covers K in [max(s*CH, kstart), min((s+1)*CH, bm+128)).
// Empty chunks exit without writing; reduce recomputes the same predicate.
// ---------------------------------------------------------------------------
__global__ __launch_bounds__(128) void k_out_part(const int* __restrict__ npadd_p) {
    const int n_padd = *npadd_p;
    const int bn = blockIdx.x * 64;
    const int bm = blockIdx.y * 128;
    const int s = blockIdx.z;
    const int kstart = (n_padd / 16) * 16;

    int lo = s * CH; if (lo < kstart) lo = kstart;
    int hi = (s + 1) * CH; if (hi > bm + 128) hi = bm + 128;
    if (lo >= hi) return;

    __shared__ float As[16][132];
    __shared__ float Bs[16][68];
    const int tid = threadIdx.x;
    const int ar = tid >> 2, ac = (tid & 3) * 4;
    const int br = tid >> 3, bc = (tid & 7) * 8;
    const int ty = tid >> 3, tx = tid & 7;

    float acc[8][8];
#pragma unroll
    for (int r = 0; r < 8; r++)
#pragma unroll
        for (int c = 0; c < 8; c++) acc[r][c] = 0.f;

    for (int k0 = lo; k0 < hi; k0 += 16) {
#pragma unroll
        for (int l = 0; l < 4; l++) {
            const int row = ar + 32 * l;
            float4 av = *(const float4*)&g_att[(size_t)(bm + row) * T + k0 + ac];
            As[ac + 0][row] = av.x;
            As[ac + 1][row] = av.y;
            As[ac + 2][row] = av.z;
            As[ac + 3][row] = av.w;
        }
        *(float4*)&Bs[br][bc] =
            *(const float4*)&g_qkv[(k0 + br) * N3 + 2 * NF + bn + bc];       // v
        *(float4*)&Bs[br][bc + 4] =
            *(const float4*)&g_qkv[(k0 + br) * N3 + 2 * NF + bn + bc + 4];
        __syncthreads();
#pragma unroll
        for (int kk = 0; kk < 16; kk++) {
            float a[8], b[8];
            *(float4*)&a[0] = *(float4*)&As[kk][ty * 8];
            *(float4*)&a[4] = *(float4*)&As[kk][ty * 8 + 4];
            *(float4*)&b[0] = *(float4*)&Bs[kk][tx * 8];
            *(float4*)&b[4] = *(float4*)&Bs[kk][tx * 8 + 4];
#pragma unroll
            for (int r = 0; r < 8; r++)
#pragma unroll
                for (int c = 0; c < 8; c++) acc[r][c] += a[r] * b[c];
        }
        __syncthreads();
    }

    float* part = &g_part[(size_t)s * T * NF];
#pragma unroll
    for (int r = 0; r < 8; r++) {
        const int row = bm + ty * 8 + r;
#pragma unroll
        for (int cc = 0; cc < 8; cc += 4) {
            const int col = bn + tx * 8 + cc;
            float4 o;
            o.x = acc[r][cc + 0]; o.y = acc[r][cc + 1];
            o.z = acc[r][cc + 2]; o.w = acc[r][cc + 3];
            *(float4*)&part[row * NF + col] = o;
        }
    }
}

// ---------------------------------------------------------------------------
// Pass 4b: deterministic reduce of valid split-K chunks; writes zeros when no
// chunk is valid (covers padded rows i < n_padd).
// ---------------------------------------------------------------------------
__global__ __launch_bounds__(256) void k_reduce(const int* __restrict__ npadd_p,
                                                float* __restrict__ out) {
    const int n_padd = *npadd_p;
    const int kstart = (n_padd / 16) * 16;
    const int idx = blockIdx.x * 256 + threadIdx.x;   // one float4 per thread
    const int i = idx >> 6;                           // NF/4 = 64 float4 per row
    const int c4 = (idx & 63) * 4;
    const int bm = (i >> 7) << 7;

    float4 acc = make_float4(0.f, 0.f, 0.f, 0.f);
#pragma unroll
    for (int s = 0; s < KSPLIT; s++) {
        int lo = s * CH; if (lo < kstart) lo = kstart;
        int hi = (s + 1) * CH; if (hi > bm + 128) hi = bm + 128;
        if (lo < hi) {
            float4 p = *(const float4*)&g_part[((size_t)s * T + i) * NF + c4];
            acc.x += p.x; acc.y += p.y; acc.z += p.z; acc.w += p.w;
        }
    }
    *(float4*)&out[i * NF + c4] = acc;
}

// ---------------------------------------------------------------------------
extern "C" void kernel_launch(void* const* d_in, const int* in_sizes, int n_in,
                              void* d_out, int out_size) {
    const float* x = (const float*)d_in[0];
    const float* W = (const float*)d_in[1];
    const float* b = (const float*)d_in[2];
    const int* n_padd = (const int*)d_in[3];
    float* out = (float*)d_out;

    k_qkv<<<dim3(N3 / 64, T / 128), 128>>>(x, W, b);
    k_scores<<<dim3(T / 128, T / 128), 256>>>(n_padd);
    k_softmax<<<T, 256>>>(n_padd);
    k_out_part<<<dim3(NF / 64, T / 128, KSPLIT), 128>>>(n_padd);
    k_reduce<<<(T * NF / 4) / 256, 256>>>(n_padd, out);
}

// round 7
// speedup vs baseline: 1.7390x; 1.2100x over previous
#include <cuda_runtime.h>
#include <cuda_bf16.h>
#include <cstdint>

#define T     4096
#define C     1024
#define NF    256
#define N3    768          // 3 * NF
#define SCALE 0.0625f      // 1/sqrt(256)
#define KSPLIT 8
#define CH    (T / KSPLIT) // 512

// Scratch (alloc-free rule: __device__ globals)
__device__ float g_qkv[T * N3];                        // 12 MB
__device__ float g_att[(size_t)T * T];                 // 64 MB
__device__ float g_part[(size_t)KSPLIT * T * NF];      // 32 MB
__device__ __nv_bfloat16 g_q_hi[T * NF];               // 2 MB each
__device__ __nv_bfloat16 g_q_lo[T * NF];
__device__ __nv_bfloat16 g_k_hi[T * NF];
__device__ __nv_bfloat16 g_k_lo[T * NF];

__device__ __forceinline__ uint32_t smem_u32(const void* p) {
    uint32_t a;
    asm("{ .reg .u64 t; cvta.to.shared.u64 t, %1; cvt.u32.u64 %0, t; }" : "=r"(a) : "l"(p));
    return a;
}

__device__ __forceinline__ void ldsm_x4(uint32_t& r0, uint32_t& r1, uint32_t& r2,
                                        uint32_t& r3, uint32_t addr) {
    asm volatile("ldmatrix.sync.aligned.m8n8.x4.shared.b16 {%0,%1,%2,%3}, [%4];"
                 : "=r"(r0), "=r"(r1), "=r"(r2), "=r"(r3) : "r"(addr));
}
__device__ __forceinline__ void ldsm_x2(uint32_t& r0, uint32_t& r1, uint32_t addr) {
    asm volatile("ldmatrix.sync.aligned.m8n8.x2.shared.b16 {%0,%1}, [%2];"
                 : "=r"(r0), "=r"(r1) : "r"(addr));
}
__device__ __forceinline__ void mma_bf16(float* c, const uint32_t* a, const uint32_t* b) {
    asm volatile(
        "mma.sync.aligned.m16n8k16.row.col.f32.bf16.bf16.f32 "
        "{%0,%1,%2,%3}, {%4,%5,%6,%7}, {%8,%9}, {%0,%1,%2,%3};"
        : "+f"(c[0]), "+f"(c[1]), "+f"(c[2]), "+f"(c[3])
        : "r"(a[0]), "r"(a[1]), "r"(a[2]), "r"(a[3]), "r"(b[0]), "r"(b[1]));
}

// ---------------------------------------------------------------------------
// Pass 1: qkv = x @ W + b    (FFMA, unchanged)
// ---------------------------------------------------------------------------
__global__ __launch_bounds__(128) void k_qkv(const float* __restrict__ x,
                                             const float* __restrict__ W,
                                             const float* __restrict__ bias) {
    __shared__ float As[16][132];
    __shared__ float Bs[16][68];
    const int tid = threadIdx.x;
    const int bm = blockIdx.y * 128;
    const int bn = blockIdx.x * 64;
    const int ar = tid >> 2, ac = (tid & 3) * 4;
    const int br = tid >> 3, bc = (tid & 7) * 8;
    const int ty = tid >> 3, tx = tid & 7;

    float acc[8][8];
#pragma unroll
    for (int r = 0; r < 8; r++)
#pragma unroll
        for (int c = 0; c < 8; c++) acc[r][c] = 0.f;

    for (int k0 = 0; k0 < C; k0 += 16) {
#pragma unroll
        for (int l = 0; l < 4; l++) {
            const int row = ar + 32 * l;
            float4 av = *(const float4*)&x[(bm + row) * C + k0 + ac];
            As[ac + 0][row] = av.x;
            As[ac + 1][row] = av.y;
            As[ac + 2][row] = av.z;
            As[ac + 3][row] = av.w;
        }
        *(float4*)&Bs[br][bc]     = *(const float4*)&W[(k0 + br) * N3 + bn + bc];
        *(float4*)&Bs[br][bc + 4] = *(const float4*)&W[(k0 + br) * N3 + bn + bc + 4];
        __syncthreads();
#pragma unroll
        for (int kk = 0; kk < 16; kk++) {
            float a[8], b[8];
            *(float4*)&a[0] = *(float4*)&As[kk][ty * 8];
            *(float4*)&a[4] = *(float4*)&As[kk][ty * 8 + 4];
            *(float4*)&b[0] = *(float4*)&Bs[kk][tx * 8];
            *(float4*)&b[4] = *(float4*)&Bs[kk][tx * 8 + 4];
#pragma unroll
            for (int r = 0; r < 8; r++)
#pragma unroll
                for (int c = 0; c < 8; c++) acc[r][c] += a[r] * b[c];
        }
        __syncthreads();
    }
#pragma unroll
    for (int r = 0; r < 8; r++) {
        const int row = bm + ty * 8 + r;
#pragma unroll
        for (int cc = 0; cc < 8; cc += 4) {
            const int col = bn + tx * 8 + cc;
            float4 o;
            o.x = acc[r][cc + 0] + bias[col + 0];
            o.y = acc[r][cc + 1] + bias[col + 1];
            o.z = acc[r][cc + 2] + bias[col + 2];
            o.w = acc[r][cc + 3] + bias[col + 3];
            *(float4*)&g_qkv[row * N3 + col] = o;
        }
    }
}

// ---------------------------------------------------------------------------
// Pass 1b: split q, k into bf16 hi/lo planes (x = hi + lo)
// ---------------------------------------------------------------------------
__global__ __launch_bounds__(256) void k_cvt() {
    const int idx = blockIdx.x * 256 + threadIdx.x;   // over T*NF/4
    const int row = idx >> 6;
    const int c = (idx & 63) * 4;
    float4 q = *(const float4*)&g_qkv[row * N3 + c];
    float4 k = *(const float4*)&g_qkv[row * N3 + NF + c];
    float qa[4] = {q.x, q.y, q.z, q.w};
    float ka[4] = {k.x, k.y, k.z, k.w};
    __nv_bfloat16 qh[4], ql[4], kh[4], kl[4];
#pragma unroll
    for (int i = 0; i < 4; i++) {
        qh[i] = __float2bfloat16(qa[i]);
        ql[i] = __float2bfloat16(qa[i] - __bfloat162float(qh[i]));
        kh[i] = __float2bfloat16(ka[i]);
        kl[i] = __float2bfloat16(ka[i] - __bfloat162float(kh[i]));
    }
    *(uint2*)&g_q_hi[row * NF + c] = *(uint2*)qh;
    *(uint2*)&g_q_lo[row * NF + c] = *(uint2*)ql;
    *(uint2*)&g_k_hi[row * NF + c] = *(uint2*)kh;
    *(uint2*)&g_k_lo[row * NF + c] = *(uint2*)kl;
}

// ---------------------------------------------------------------------------
// Pass 2 (HMMA): att 128x128 tile = q @ k^T, split-precision bf16 via
// mma.sync.m16n8k16 (hh + hl + lh combos, fp32 accumulate).
// 8 warps in 2(m) x 4(n); warp tile 64x32. K chunked by 64.
// ---------------------------------------------------------------------------
#define BKP 72                       // padded row: 64 bf16 + 8 pad (144 B)
#define PLANE (128 * BKP * 2)        // bytes per smem plane = 18432

__global__ __launch_bounds__(256) void k_scores_mma(const int* __restrict__ npadd_p) {
    const int n_padd = *npadd_p;
    const int bm = blockIdx.y * 128;   // i block
    const int bn = blockIdx.x * 128;   // j block
    if (bn > bm) return;               // strictly above diagonal: never read later

    const int tid = threadIdx.x;

    // Fully-masked tiles: zero-fill, skip GEMM
    if (bn + 127 < n_padd || bm + 127 < n_padd) {
        const int i = bm + (tid >> 1);
        const int c0 = (tid & 1) * 64;
#pragma unroll
        for (int c = 0; c < 64; c += 4)
            *(float4*)&g_att[(size_t)i * T + bn + c0 + c] = make_float4(0.f, 0.f, 0.f, 0.f);
        return;
    }

    extern __shared__ char dyn[];
    const uint32_t sb = smem_u32(dyn);
    const uint32_t sAh = sb, sAl = sb + PLANE, sBh = sb + 2 * PLANE, sBl = sb + 3 * PLANE;

    const int wid = tid >> 5, lane = tid & 31;
    const int warp_m = wid >> 2, warp_n = wid & 3;     // 2 x 4
    const int rw = tid >> 1, half = tid & 1;           // loaders: 2 thr/row

    float acc[4][4][4];
#pragma unroll
    for (int fm = 0; fm < 4; fm++)
#pragma unroll
        for (int fn = 0; fn < 4; fn++)
#pragma unroll
            for (int e = 0; e < 4; e++) acc[fm][fn][e] = 0.f;

    for (int k0 = 0; k0 < NF; k0 += 64) {
        // ---- load 4 planes: rows 0..127, cols k0..k0+63 ----
#pragma unroll
        for (int j = 0; j < 4; j++) {
            const int c16 = half * 4 + j;                 // 16-byte group 0..7
            const int gofs = k0 + c16 * 8;
            const uint32_t so = (uint32_t)(rw * (BKP * 2) + c16 * 16);
            *(uint4*)(dyn + 0 * PLANE + so) = *(const uint4*)&g_q_hi[(bm + rw) * NF + gofs];
            *(uint4*)(dyn + 1 * PLANE + so) = *(const uint4*)&g_q_lo[(bm + rw) * NF + gofs];
            *(uint4*)(dyn + 2 * PLANE + so) = *(const uint4*)&g_k_hi[(bn + rw) * NF + gofs];
            *(uint4*)(dyn + 3 * PLANE + so) = *(const uint4*)&g_k_lo[(bn + rw) * NF + gofs];
        }
        __syncthreads();

        // ---- compute: 4 kk16 steps ----
#pragma unroll
        for (int kk = 0; kk < 4; kk++) {
            uint32_t ah[4][4], al[4][4], bh[4][2], bl[4][2];
            // A frags: rows warp_m*64 + fm*16 + (lane&15), col 16B-group (lane>>4)
            const int a_row = warp_m * 64 + (lane & 15);
            const uint32_t a_cb = (uint32_t)(kk * 32 + (lane >> 4) * 16);
#pragma unroll
            for (int fm = 0; fm < 4; fm++) {
                const uint32_t off = (uint32_t)((a_row + fm * 16) * (BKP * 2)) + a_cb;
                ldsm_x4(ah[fm][0], ah[fm][1], ah[fm][2], ah[fm][3], sAh + off);
                ldsm_x4(al[fm][0], al[fm][1], al[fm][2], al[fm][3], sAl + off);
            }
            // B frags: rows warp_n*32 + fn*8 + (lane&7), col group ((lane>>3)&1)
            const int b_row = warp_n * 32 + (lane & 7);
            const uint32_t b_cb = (uint32_t)(kk * 32 + ((lane >> 3) & 1) * 16);
#pragma unroll
            for (int fn = 0; fn < 4; fn++) {
                const uint32_t off = (uint32_t)((b_row + fn * 8) * (BKP * 2)) + b_cb;
                ldsm_x2(bh[fn][0], bh[fn][1], sBh + off);
                ldsm_x2(bl[fn][0], bl[fn][1], sBl + off);
            }
#pragma unroll
            for (int fm = 0; fm < 4; fm++)
#pragma unroll
                for (int fn = 0; fn < 4; fn++) {
                    mma_bf16(acc[fm][fn], ah[fm], bh[fn]);   // hi*hi
                    mma_bf16(acc[fm][fn], ah[fm], bl[fn]);   // hi*lo
                    mma_bf16(acc[fm][fn], al[fm], bh[fn]);   // lo*hi
                }
        }
        __syncthreads();
    }

    // ---- epilogue: mask + scale, write att ----
    const int er = lane >> 2, ec = (lane & 3) * 2;
#pragma unroll
    for (int fm = 0; fm < 4; fm++) {
#pragma unroll
        for (int fn = 0; fn < 4; fn++) {
            const int col = bn + warp_n * 32 + fn * 8 + ec;
#pragma unroll
            for (int h = 0; h < 2; h++) {                  // row halves +0, +8
                const int i = bm + warp_m * 64 + fm * 16 + er + h * 8;
                float2 o;
                const float v0 = acc[fm][fn][h * 2 + 0];
                const float v1 = acc[fm][fn][h * 2 + 1];
                o.x = (col + 0 <= i && col + 0 >= n_padd) ? v0 * SCALE : 0.f;
                o.y = (col + 1 <= i && col + 1 >= n_padd) ? v1 * SCALE : 0.f;
                *(float2*)&g_att[(size_t)i * T + col] = o;
            }
        }
    }
}

// ---------------------------------------------------------------------------
// Pass 3: row softmax over att[i][n_padd .. i]
// ---------------------------------------------------------------------------
__global__ __launch_bounds__(256) void k_softmax(const int* __restrict__ npadd_p) {
    const int n_padd = *npadd_p;
    const int i = blockIdx.x;
    if (i < n_padd) return;
    const int L = i - n_padd + 1;

    __shared__ float row[T];
    __shared__ float red[8];
    float* att = &g_att[(size_t)i * T + n_padd];
    const int tid = threadIdx.x;
    const int lane = tid & 31, wid = tid >> 5;

    float m = -3.4e38f;
    for (int j = tid; j < L; j += 256) {
        const float v = att[j];
        row[j] = v;
        m = fmaxf(m, v);
    }
#pragma unroll
    for (int s = 16; s > 0; s >>= 1) m = fmaxf(m, __shfl_xor_sync(0xffffffffu, m, s));
    if (lane == 0) red[wid] = m;
    __syncthreads();
    m = red[0];
#pragma unroll
    for (int w = 1; w < 8; w++) m = fmaxf(m, red[w]);
    __syncthreads();

    float sum = 0.f;
    for (int j = tid; j < L; j += 256) {
        const float e = __expf(row[j] - m);
        row[j] = e;
        sum += e;
    }
#pragma unroll
    for (int s = 16; s > 0; s >>= 1) sum += __shfl_xor_sync(0xffffffffu, sum, s);
    if (lane == 0) red[wid] = sum;
    __syncthreads();
    sum = red[0];
#pragma unroll
    for (int w = 1; w < 8; w++) sum += red[w];

    const float inv = 1.f / sum;
    for (int j = tid; j < L; j += 256) att[j] = row[j] * inv;
}

// ---------------------------------------------------------------------------
// Pass 4a: split-K partials of y = p @ v  (FFMA, unchanged)
// ---------------------------------------------------------------------------
__global__ __launch_bounds__(128) void k_out_part(const int* __restrict__ npadd_p) {
    const int n_padd = *npadd_p;
    const int bn = blockIdx.x * 64;
    const int bm = blockIdx.y * 128;
    const int s = blockIdx.z;
    const int kstart = (n_padd / 16) * 16;

    int lo = s * CH; if (lo < kstart) lo = kstart;
    int hi = (s + 1) * CH; if (hi > bm + 128) hi = bm + 128;
    if (lo >= hi) return;

    __shared__ float As[16][132];
    __shared__ float Bs[16][68];
    const int tid = threadIdx.x;
    const int ar = tid >> 2, ac = (tid & 3) * 4;
    const int br = tid >> 3, bc = (tid & 7) * 8;
    const int ty = tid >> 3, tx = tid & 7;

    float acc[8][8];
#pragma unroll
    for (int r = 0; r < 8; r++)
#pragma unroll
        for (int c = 0; c < 8; c++) acc[r][c] = 0.f;

    for (int k0 = lo; k0 < hi; k0 += 16) {
#pragma unroll
        for (int l = 0; l < 4; l++) {
            const int row = ar + 32 * l;
            float4 av = *(const float4*)&g_att[(size_t)(bm + row) * T + k0 + ac];
            As[ac + 0][row] = av.x;
            As[ac + 1][row] = av.y;
            As[ac + 2][row] = av.z;
            As[ac + 3][row] = av.w;
        }
        *(float4*)&Bs[br][bc] =
            *(const float4*)&g_qkv[(k0 + br) * N3 + 2 * NF + bn + bc];
        *(float4*)&Bs[br][bc + 4] =
            *(const float4*)&g_qkv[(k0 + br) * N3 + 2 * NF + bn + bc + 4];
        __syncthreads();
#pragma unroll
        for (int kk = 0; kk < 16; kk++) {
            float a[8], b[8];
            *(float4*)&a[0] = *(float4*)&As[kk][ty * 8];
            *(float4*)&a[4] = *(float4*)&As[kk][ty * 8 + 4];
            *(float4*)&b[0] = *(float4*)&Bs[kk][tx * 8];
            *(float4*)&b[4] = *(float4*)&Bs[kk][tx * 8 + 4];
#pragma unroll
            for (int r = 0; r < 8; r++)
#pragma unroll
                for (int c = 0; c < 8; c++) acc[r][c] += a[r] * b[c];
        }
        __syncthreads();
    }

    float* part = &g_part[(size_t)s * T * NF];
#pragma unroll
    for (int r = 0; r < 8; r++) {
        const int row = bm + ty * 8 + r;
#pragma unroll
        for (int cc = 0; cc < 8; cc += 4) {
            const int col = bn + tx * 8 + cc;
            float4 o;
            o.x = acc[r][cc + 0]; o.y = acc[r][cc + 1];
            o.z = acc[r][cc + 2]; o.w = acc[r][cc + 3];
            *(float4*)&part[row * NF + col] = o;
        }
    }
}

// ---------------------------------------------------------------------------
// Pass 4b: deterministic reduce of valid split-K chunks
// ---------------------------------------------------------------------------
__global__ __launch_bounds__(256) void k_reduce(const int* __restrict__ npadd_p,
                                                float* __restrict__ out) {
    const int n_padd = *npadd_p;
    const int kstart = (n_padd / 16) * 16;
    const int idx = blockIdx.x * 256 + threadIdx.x;
    const int i = idx >> 6;
    const int c4 = (idx & 63) * 4;
    const int bm = (i >> 7) << 7;

    float4 acc = make_float4(0.f, 0.f, 0.f, 0.f);
#pragma unroll
    for (int s = 0; s < KSPLIT; s++) {
        int lo = s * CH; if (lo < kstart) lo = kstart;
        int hi = (s + 1) * CH; if (hi > bm + 128) hi = bm + 128;
        if (lo < hi) {
            float4 p = *(const float4*)&g_part[((size_t)s * T + i) * NF + c4];
            acc.x += p.x; acc.y += p.y; acc.z += p.z; acc.w += p.w;
        }
    }
    *(float4*)&out[i * NF + c4] = acc;
}

// ---------------------------------------------------------------------------
extern "C" void kernel_launch(void* const* d_in, const int* in_sizes, int n_in,
                              void* d_out, int out_size) {
    const float* x = (const float*)d_in[0];
    const float* W = (const float*)d_in[1];
    const float* b = (const float*)d_in[2];
    const int* n_padd = (const int*)d_in[3];
    float* out = (float*)d_out;

    cudaFuncSetAttribute(k_scores_mma, cudaFuncAttributeMaxDynamicSharedMemorySize,
                         4 * PLANE);

    k_qkv<<<dim3(N3 / 64, T / 128), 128>>>(x, W, b);
    k_cvt<<<(T * NF / 4) / 256, 256>>>();
    k_scores_mma<<<dim3(T / 128, T / 128), 256, 4 * PLANE>>>(n_padd);
    k_softmax<<<T, 256>>>(n_padd);
    k_out_part<<<dim3(NF / 64, T / 128, KSPLIT), 128>>>(n_padd);
    k_reduce<<<(T * NF / 4) / 256, 256>>>(n_padd, out);
}

// round 8
// speedup vs baseline: 2.4248x; 1.3944x over previous
#include <cuda_runtime.h>
#include <cuda_bf16.h>
#include <cstdint>

#define T     4096
#define C     1024
#define NF    256
#define N3    768          // 3 * NF
#define SCALE 0.0625f      // 1/sqrt(256)
#define KSPLIT 8
#define CH    (T / KSPLIT) // 512

// Scratch (alloc-free rule: __device__ globals)
__device__ float g_qkv[T * N3];                        // 12 MB
__device__ float g_att[(size_t)T * T];                 // 64 MB (scores, read by softmax only)
__device__ float g_part[(size_t)KSPLIT * T * NF];      // 32 MB split-K partials
__device__ __nv_bfloat16 g_x_hi[T * C];                // 8 MB each
__device__ __nv_bfloat16 g_x_lo[T * C];
__device__ __nv_bfloat16 g_wT_hi[N3 * C];              // 1.5 MB each, [n][k]
__device__ __nv_bfloat16 g_wT_lo[N3 * C];
__device__ __nv_bfloat16 g_q_hi[T * NF];               // 2 MB each
__device__ __nv_bfloat16 g_q_lo[T * NF];
__device__ __nv_bfloat16 g_k_hi[T * NF];
__device__ __nv_bfloat16 g_k_lo[T * NF];
__device__ __nv_bfloat16 g_vT_hi[NF * T];              // 2 MB each, [n][k]
__device__ __nv_bfloat16 g_vT_lo[NF * T];
__device__ __nv_bfloat16 g_p_hi[(size_t)T * T];        // 32 MB each
__device__ __nv_bfloat16 g_p_lo[(size_t)T * T];

__device__ __forceinline__ uint32_t smem_u32(const void* p) {
    uint32_t a;
    asm("{ .reg .u64 t; cvta.to.shared.u64 t, %1; cvt.u32.u64 %0, t; }" : "=r"(a) : "l"(p));
    return a;
}
__device__ __forceinline__ void ldsm_x4(uint32_t& r0, uint32_t& r1, uint32_t& r2,
                                        uint32_t& r3, uint32_t addr) {
    asm volatile("ldmatrix.sync.aligned.m8n8.x4.shared.b16 {%0,%1,%2,%3}, [%4];"
                 : "=r"(r0), "=r"(r1), "=r"(r2), "=r"(r3) : "r"(addr));
}
__device__ __forceinline__ void ldsm_x2(uint32_t& r0, uint32_t& r1, uint32_t addr) {
    asm volatile("ldmatrix.sync.aligned.m8n8.x2.shared.b16 {%0,%1}, [%2];"
                 : "=r"(r0), "=r"(r1) : "r"(addr));
}
__device__ __forceinline__ void mma_bf16(float* c, const uint32_t* a, const uint32_t* b) {
    asm volatile(
        "mma.sync.aligned.m16n8k16.row.col.f32.bf16.bf16.f32 "
        "{%0,%1,%2,%3}, {%4,%5,%6,%7}, {%8,%9}, {%0,%1,%2,%3};"
        : "+f"(c[0]), "+f"(c[1]), "+f"(c[2]), "+f"(c[3])
        : "r"(a[0]), "r"(a[1]), "r"(a[2]), "r"(a[3]), "r"(b[0]), "r"(b[1]));
}

#define BKP 72                       // padded row: 64 bf16 + 8 pad (144 B)
#define PLANE (128 * BKP * 2)        // bytes per smem plane = 18432

// ---------------------------------------------------------------------------
// Generic 128x128 HMMA tile body: loads 4 planes (Ah, Al, Bh, Bl) rows from
// given gmem base pointers with row stride `gstride`, K chunk at k0 (+64),
// then does 4 kk16 steps of 3-combo split-precision MMA into acc[4][4][4].
// Shared by qkv / scores / out kernels via macro to keep identical layout.
// ---------------------------------------------------------------------------
#define LOAD_PLANES(Ah, Al, Bh, Bl, aRow, bRow, gstride, k0)                          \
    {                                                                                  \
        _Pragma("unroll")                                                              \
        for (int j = 0; j < 4; j++) {                                                  \
            const int c16 = half * 4 + j;                                              \
            const int gofs = (k0) + c16 * 8;                                           \
            const uint32_t so = (uint32_t)(rw * (BKP * 2) + c16 * 16);                 \
            *(uint4*)(dyn + 0 * PLANE + so) = *(const uint4*)&(Ah)[(size_t)(aRow) * (gstride) + gofs]; \
            *(uint4*)(dyn + 1 * PLANE + so) = *(const uint4*)&(Al)[(size_t)(aRow) * (gstride) + gofs]; \
            *(uint4*)(dyn + 2 * PLANE + so) = *(const uint4*)&(Bh)[(size_t)(bRow) * (gstride) + gofs]; \
            *(uint4*)(dyn + 3 * PLANE + so) = *(const uint4*)&(Bl)[(size_t)(bRow) * (gstride) + gofs]; \
        }                                                                              \
    }

#define COMPUTE_CHUNK(sAh, sAl, sBh, sBl)                                              \
    {                                                                                  \
        _Pragma("unroll")                                                              \
        for (int kk = 0; kk < 4; kk++) {                                               \
            uint32_t ah[4][4], al[4][4], bh[4][2], bl[4][2];                           \
            const int a_row = warp_m * 64 + (lane & 15);                               \
            const uint32_t a_cb = (uint32_t)(kk * 32 + (lane >> 4) * 16);              \
            _Pragma("unroll")                                                          \
            for (int fm = 0; fm < 4; fm++) {                                           \
                const uint32_t off = (uint32_t)((a_row + fm * 16) * (BKP * 2)) + a_cb; \
                ldsm_x4(ah[fm][0], ah[fm][1], ah[fm][2], ah[fm][3], (sAh) + off);      \
                ldsm_x4(al[fm][0], al[fm][1], al[fm][2], al[fm][3], (sAl) + off);      \
            }                                                                          \
            const int b_row = warp_n * 32 + (lane & 7);                                \
            const uint32_t b_cb = (uint32_t)(kk * 32 + ((lane >> 3) & 1) * 16);        \
            _Pragma("unroll")                                                          \
            for (int fn = 0; fn < 4; fn++) {                                           \
                const uint32_t off = (uint32_t)((b_row + fn * 8) * (BKP * 2)) + b_cb;  \
                ldsm_x2(bh[fn][0], bh[fn][1], (sBh) + off);                            \
                ldsm_x2(bl[fn][0], bl[fn][1], (sBl) + off);                            \
            }                                                                          \
            _Pragma("unroll")                                                          \
            for (int fm = 0; fm < 4; fm++)                                             \
                _Pragma("unroll")                                                      \
                for (int fn = 0; fn < 4; fn++) {                                       \
                    mma_bf16(acc[fm][fn], ah[fm], bh[fn]);                             \
                    mma_bf16(acc[fm][fn], ah[fm], bl[fn]);                             \
                    mma_bf16(acc[fm][fn], al[fm], bh[fn]);                             \
                }                                                                      \
        }                                                                              \
    }

// ---------------------------------------------------------------------------
// Input conversions
// ---------------------------------------------------------------------------
__global__ __launch_bounds__(256) void k_cvt_x(const float* __restrict__ x) {
    const int idx = blockIdx.x * 256 + threadIdx.x;     // over T*C/4
    const int base = idx * 4;
    float4 v = *(const float4*)&x[base];
    float a[4] = {v.x, v.y, v.z, v.w};
    __nv_bfloat16 h[4], l[4];
#pragma unroll
    for (int i = 0; i < 4; i++) {
        h[i] = __float2bfloat16(a[i]);
        l[i] = __float2bfloat16(a[i] - __bfloat162float(h[i]));
    }
    *(uint2*)&g_x_hi[base] = *(uint2*)h;
    *(uint2*)&g_x_lo[base] = *(uint2*)l;
}

// W[k][n] (k=0..C-1 rows, n=0..N3-1 cols) -> wT[n][k], hi/lo split
__global__ void k_cvt_w(const float* __restrict__ W) {
    __shared__ float tile[32][33];
    const int c0 = blockIdx.x * 32;   // n block
    const int r0 = blockIdx.y * 32;   // k block
    const int tx = threadIdx.x, ty = threadIdx.y;
#pragma unroll
    for (int yy = ty; yy < 32; yy += 8)
        tile[yy][tx] = W[(size_t)(r0 + yy) * N3 + c0 + tx];
    __syncthreads();
#pragma unroll
    for (int yy = ty; yy < 32; yy += 8) {
        const float v = tile[tx][yy];
        const __nv_bfloat16 h = __float2bfloat16(v);
        const __nv_bfloat16 l = __float2bfloat16(v - __bfloat162float(h));
        g_wT_hi[(size_t)(c0 + yy) * C + r0 + tx] = h;
        g_wT_lo[(size_t)(c0 + yy) * C + r0 + tx] = l;
    }
}

// ---------------------------------------------------------------------------
// Pass 1 (HMMA): qkv = x @ W + b.  Grid (N3/128, T/128) = (6, 32).
// ---------------------------------------------------------------------------
__global__ __launch_bounds__(256) void k_qkv_mma(const float* __restrict__ bias) {
    const int bm = blockIdx.y * 128;
    const int bn = blockIdx.x * 128;
    const int tid = threadIdx.x;
    extern __shared__ char dyn[];
    const uint32_t sb = smem_u32(dyn);
    const uint32_t sAh = sb, sAl = sb + PLANE, sBh = sb + 2 * PLANE, sBl = sb + 3 * PLANE;
    const int wid = tid >> 5, lane = tid & 31;
    const int warp_m = wid >> 2, warp_n = wid & 3;
    const int rw = tid >> 1, half = tid & 1;

    float acc[4][4][4];
#pragma unroll
    for (int fm = 0; fm < 4; fm++)
#pragma unroll
        for (int fn = 0; fn < 4; fn++)
#pragma unroll
            for (int e = 0; e < 4; e++) acc[fm][fn][e] = 0.f;

    for (int k0 = 0; k0 < C; k0 += 64) {
        LOAD_PLANES(g_x_hi, g_x_lo, g_wT_hi, g_wT_lo, bm + rw, bn + rw, C, k0);
        __syncthreads();
        COMPUTE_CHUNK(sAh, sAl, sBh, sBl);
        __syncthreads();
    }

    const int er = lane >> 2, ec = (lane & 3) * 2;
#pragma unroll
    for (int fm = 0; fm < 4; fm++)
#pragma unroll
        for (int fn = 0; fn < 4; fn++) {
            const int col = bn + warp_n * 32 + fn * 8 + ec;
            const float b0 = bias[col], b1 = bias[col + 1];
#pragma unroll
            for (int h = 0; h < 2; h++) {
                const int row = bm + warp_m * 64 + fm * 16 + er + h * 8;
                float2 o;
                o.x = acc[fm][fn][h * 2 + 0] + b0;
                o.y = acc[fm][fn][h * 2 + 1] + b1;
                *(float2*)&g_qkv[(size_t)row * N3 + col] = o;
            }
        }
}

// ---------------------------------------------------------------------------
// Pass 1b: split q, k into bf16 hi/lo planes
// ---------------------------------------------------------------------------
__global__ __launch_bounds__(256) void k_cvt_qk() {
    const int idx = blockIdx.x * 256 + threadIdx.x;   // over T*NF/4
    const int row = idx >> 6;
    const int c = (idx & 63) * 4;
    float4 q = *(const float4*)&g_qkv[(size_t)row * N3 + c];
    float4 k = *(const float4*)&g_qkv[(size_t)row * N3 + NF + c];
    float qa[4] = {q.x, q.y, q.z, q.w};
    float ka[4] = {k.x, k.y, k.z, k.w};
    __nv_bfloat16 qh[4], ql[4], kh[4], kl[4];
#pragma unroll
    for (int i = 0; i < 4; i++) {
        qh[i] = __float2bfloat16(qa[i]);
        ql[i] = __float2bfloat16(qa[i] - __bfloat162float(qh[i]));
        kh[i] = __float2bfloat16(ka[i]);
        kl[i] = __float2bfloat16(ka[i] - __bfloat162float(kh[i]));
    }
    *(uint2*)&g_q_hi[row * NF + c] = *(uint2*)qh;
    *(uint2*)&g_q_lo[row * NF + c] = *(uint2*)ql;
    *(uint2*)&g_k_hi[row * NF + c] = *(uint2*)kh;
    *(uint2*)&g_k_lo[row * NF + c] = *(uint2*)kl;
}

// v = qkv[:, 2NF:3NF]  ->  vT[n][k] hi/lo (transposed)
__global__ void k_cvt_v() {
    __shared__ float tile[32][33];
    const int c0 = blockIdx.x * 32;   // n block (0..NF)
    const int r0 = blockIdx.y * 32;   // j block (0..T)
    const int tx = threadIdx.x, ty = threadIdx.y;
#pragma unroll
    for (int yy = ty; yy < 32; yy += 8)
        tile[yy][tx] = g_qkv[(size_t)(r0 + yy) * N3 + 2 * NF + c0 + tx];
    __syncthreads();
#pragma unroll
    for (int yy = ty; yy < 32; yy += 8) {
        const float v = tile[tx][yy];
        const __nv_bfloat16 h = __float2bfloat16(v);
        const __nv_bfloat16 l = __float2bfloat16(v - __bfloat162float(h));
        g_vT_hi[(size_t)(c0 + yy) * T + r0 + tx] = h;
        g_vT_lo[(size_t)(c0 + yy) * T + r0 + tx] = l;
    }
}

// ---------------------------------------------------------------------------
// Pass 2 (HMMA): scores 128x128 tile = q @ k^T; writes fp32 att (read by
// softmax only — masked tiles are skipped, never read).
// ---------------------------------------------------------------------------
__global__ __launch_bounds__(256) void k_scores_mma(const int* __restrict__ npadd_p) {
    const int n_padd = *npadd_p;
    const int bm = blockIdx.y * 128;
    const int bn = blockIdx.x * 128;
    if (bn > bm) return;
    if (bn + 127 < n_padd || bm + 127 < n_padd) return;   // never read downstream

    const int tid = threadIdx.x;
    extern __shared__ char dyn[];
    const uint32_t sb = smem_u32(dyn);
    const uint32_t sAh = sb, sAl = sb + PLANE, sBh = sb + 2 * PLANE, sBl = sb + 3 * PLANE;
    const int wid = tid >> 5, lane = tid & 31;
    const int warp_m = wid >> 2, warp_n = wid & 3;
    const int rw = tid >> 1, half = tid & 1;

    float acc[4][4][4];
#pragma unroll
    for (int fm = 0; fm < 4; fm++)
#pragma unroll
        for (int fn = 0; fn < 4; fn++)
#pragma unroll
            for (int e = 0; e < 4; e++) acc[fm][fn][e] = 0.f;

    for (int k0 = 0; k0 < NF; k0 += 64) {
        LOAD_PLANES(g_q_hi, g_q_lo, g_k_hi, g_k_lo, bm + rw, bn + rw, NF, k0);
        __syncthreads();
        COMPUTE_CHUNK(sAh, sAl, sBh, sBl);
        __syncthreads();
    }

    const int er = lane >> 2, ec = (lane & 3) * 2;
#pragma unroll
    for (int fm = 0; fm < 4; fm++)
#pragma unroll
        for (int fn = 0; fn < 4; fn++) {
            const int col = bn + warp_n * 32 + fn * 8 + ec;
#pragma unroll
            for (int h = 0; h < 2; h++) {
                const int i = bm + warp_m * 64 + fm * 16 + er + h * 8;
                float2 o;
                o.x = acc[fm][fn][h * 2 + 0] * SCALE;
                o.y = acc[fm][fn][h * 2 + 1] * SCALE;
                *(float2*)&g_att[(size_t)i * T + col] = o;
            }
        }
}

// ---------------------------------------------------------------------------
// Pass 3: row softmax; emits p as bf16 hi/lo FULL rows (zeros outside
// [n_padd, i]) so the out-GEMM can read tiles blindly.
// ---------------------------------------------------------------------------
__global__ __launch_bounds__(256) void k_softmax(const int* __restrict__ npadd_p) {
    const int n_padd = *npadd_p;
    const int i = blockIdx.x;
    const int tid = threadIdx.x;
    __nv_bfloat16* ph = &g_p_hi[(size_t)i * T];
    __nv_bfloat16* pl = &g_p_lo[(size_t)i * T];

    if (i < n_padd) {
        const __nv_bfloat16 z = __float2bfloat16(0.f);
        for (int j = tid; j < T; j += 256) { ph[j] = z; pl[j] = z; }
        return;
    }
    const int L = i - n_padd + 1;

    __shared__ float row[T];
    __shared__ float red[8];
    const float* att = &g_att[(size_t)i * T + n_padd];
    const int lane = tid & 31, wid = tid >> 5;

    float m = -3.4e38f;
    for (int j = tid; j < L; j += 256) {
        const float v = att[j];
        row[j] = v;
        m = fmaxf(m, v);
    }
#pragma unroll
    for (int s = 16; s > 0; s >>= 1) m = fmaxf(m, __shfl_xor_sync(0xffffffffu, m, s));
    if (lane == 0) red[wid] = m;
    __syncthreads();
    m = red[0];
#pragma unroll
    for (int w = 1; w < 8; w++) m = fmaxf(m, red[w]);
    __syncthreads();

    float sum = 0.f;
    for (int j = tid; j < L; j += 256) {
        const float e = __expf(row[j] - m);
        row[j] = e;
        sum += e;
    }
#pragma unroll
    for (int s = 16; s > 0; s >>= 1) sum += __shfl_xor_sync(0xffffffffu, sum, s);
    if (lane == 0) red[wid] = sum;
    __syncthreads();
    sum = red[0];
#pragma unroll
    for (int w = 1; w < 8; w++) sum += red[w];
    const float inv = 1.f / sum;

    const __nv_bfloat16 z = __float2bfloat16(0.f);
    for (int j = tid; j < T; j += 256) {
        if (j >= n_padd && j <= i) {
            const float p = row[j - n_padd] * inv;
            const __nv_bfloat16 h = __float2bfloat16(p);
            ph[j] = h;
            pl[j] = __float2bfloat16(p - __bfloat162float(h));
        } else {
            ph[j] = z;
            pl[j] = z;
        }
    }
}

// ---------------------------------------------------------------------------
// Pass 4a (HMMA): split-K partials of y = p @ v.
// Grid (NF/128, T/128, KSPLIT) = (2, 32, 8). 128x128 tile, BK=64.
// Chunk s covers K in [max(s*CH, kstart64), min((s+1)*CH, bm+128)).
// ---------------------------------------------------------------------------
__global__ __launch_bounds__(256) void k_out_mma(const int* __restrict__ npadd_p) {
    const int n_padd = *npadd_p;
    const int bn = blockIdx.x * 128;
    const int bm = blockIdx.y * 128;
    const int s = blockIdx.z;
    const int kstart = (n_padd / 64) * 64;

    int lo = s * CH; if (lo < kstart) lo = kstart;
    int hi = (s + 1) * CH; if (hi > bm + 128) hi = bm + 128;
    if (lo >= hi) return;

    const int tid = threadIdx.x;
    extern __shared__ char dyn[];
    const uint32_t sb = smem_u32(dyn);
    const uint32_t sAh = sb, sAl = sb + PLANE, sBh = sb + 2 * PLANE, sBl = sb + 3 * PLANE;
    const int wid = tid >> 5, lane = tid & 31;
    const int warp_m = wid >> 2, warp_n = wid & 3;
    const int rw = tid >> 1, half = tid & 1;

    float acc[4][4][4];
#pragma unroll
    for (int fm = 0; fm < 4; fm++)
#pragma unroll
        for (int fn = 0; fn < 4; fn++)
#pragma unroll
            for (int e = 0; e < 4; e++) acc[fm][fn][e] = 0.f;

    for (int k0 = lo; k0 < hi; k0 += 64) {
        LOAD_PLANES(g_p_hi, g_p_lo, g_vT_hi, g_vT_lo, bm + rw, bn + rw, T, k0);
        __syncthreads();
        COMPUTE_CHUNK(sAh, sAl, sBh, sBl);
        __syncthreads();
    }

    float* part = &g_part[(size_t)s * T * NF];
    const int er = lane >> 2, ec = (lane & 3) * 2;
#pragma unroll
    for (int fm = 0; fm < 4; fm++)
#pragma unroll
        for (int fn = 0; fn < 4; fn++) {
            const int col = bn + warp_n * 32 + fn * 8 + ec;
#pragma unroll
            for (int h = 0; h < 2; h++) {
                const int row = bm + warp_m * 64 + fm * 16 + er + h * 8;
                float2 o;
                o.x = acc[fm][fn][h * 2 + 0];
                o.y = acc[fm][fn][h * 2 + 1];
                *(float2*)&part[(size_t)row * NF + col] = o;
            }
        }
}

// ---------------------------------------------------------------------------
// Pass 4b: deterministic reduce (predicate mirrors k_out_mma exactly)
// ---------------------------------------------------------------------------
__global__ __launch_bounds__(256) void k_reduce(const int* __restrict__ npadd_p,
                                                float* __restrict__ out) {
    const int n_padd = *npadd_p;
    const int kstart = (n_padd / 64) * 64;
    const int idx = blockIdx.x * 256 + threadIdx.x;
    const int i = idx >> 6;
    const int c4 = (idx & 63) * 4;
    const int bm = (i >> 7) << 7;

    float4 acc = make_float4(0.f, 0.f, 0.f, 0.f);
#pragma unroll
    for (int s = 0; s < KSPLIT; s++) {
        int lo = s * CH; if (lo < kstart) lo = kstart;
        int hi = (s + 1) * CH; if (hi > bm + 128) hi = bm + 128;
        if (lo < hi) {
            float4 p = *(const float4*)&g_part[((size_t)s * T + i) * NF + c4];
            acc.x += p.x; acc.y += p.y; acc.z += p.z; acc.w += p.w;
        }
    }
    *(float4*)&out[(size_t)i * NF + c4] = acc;
}

// ---------------------------------------------------------------------------
extern "C" void kernel_launch(void* const* d_in, const int* in_sizes, int n_in,
                              void* d_out, int out_size) {
    const float* x = (const float*)d_in[0];
    const float* W = (const float*)d_in[1];
    const float* b = (const float*)d_in[2];
    const int* n_padd = (const int*)d_in[3];
    float* out = (float*)d_out;

    cudaFuncSetAttribute(k_qkv_mma,    cudaFuncAttributeMaxDynamicSharedMemorySize, 4 * PLANE);
    cudaFuncSetAttribute(k_scores_mma, cudaFuncAttributeMaxDynamicSharedMemorySize, 4 * PLANE);
    cudaFuncSetAttribute(k_out_mma,    cudaFuncAttributeMaxDynamicSharedMemorySize, 4 * PLANE);

    k_cvt_x<<<(T * C / 4) / 256, 256>>>(x);
    k_cvt_w<<<dim3(N3 / 32, C / 32), dim3(32, 8)>>>(W);
    k_qkv_mma<<<dim3(N3 / 128, T / 128), 256, 4 * PLANE>>>(b);
    k_cvt_qk<<<(T * NF / 4) / 256, 256>>>();
    k_cvt_v<<<dim3(NF / 32, T / 32), dim3(32, 8)>>>();
    k_scores_mma<<<dim3(T / 128, T / 128), 256, 4 * PLANE>>>(n_padd);
    k_softmax<<<T, 256>>>(n_padd);
    k_out_mma<<<dim3(NF / 128, T / 128, KSPLIT), 256, 4 * PLANE>>>(n_padd);
    k_reduce<<<(T * NF / 4) / 256, 256>>>(n_padd, out);
}

// round 9
// speedup vs baseline: 2.6279x; 1.0838x over previous
#include <cuda_runtime.h>
#include <cuda_bf16.h>
#include <cstdint>

#define T      4096
#define C      1024
#define NF     256
#define N3     768          // 3 * NF
#define SCALE  0.0625f      // 1/sqrt(256)
#define NEGINF -1e30f
#define JSPLIT 4
#define JCH    (T / JSPLIT) // 1024

// Scratch (alloc-free rule: __device__ globals)
__device__ float g_qkv[T * N3];                        // 12 MB
__device__ __nv_bfloat16 g_x_hi[T * C];                // 8 MB each
__device__ __nv_bfloat16 g_x_lo[T * C];
__device__ __nv_bfloat16 g_wT_hi[N3 * C];              // 1.5 MB each, [n][k]
__device__ __nv_bfloat16 g_wT_lo[N3 * C];
__device__ __nv_bfloat16 g_q_hi[T * NF];               // 2 MB each
__device__ __nv_bfloat16 g_q_lo[T * NF];
__device__ __nv_bfloat16 g_k_hi[T * NF];
__device__ __nv_bfloat16 g_k_lo[T * NF];
__device__ __nv_bfloat16 g_vT_hi[NF * T];              // 2 MB each, [n][k]
__device__ __nv_bfloat16 g_vT_lo[NF * T];
__device__ float g_fy[(size_t)JSPLIT * T * NF];        // 16 MB unnormalized Y partials
__device__ float g_fm[JSPLIT * T];                     // row max per chunk
__device__ float g_fl[JSPLIT * T];                     // row sum per chunk

__device__ __forceinline__ uint32_t smem_u32(const void* p) {
    uint32_t a;
    asm("{ .reg .u64 t; cvta.to.shared.u64 t, %1; cvt.u32.u64 %0, t; }" : "=r"(a) : "l"(p));
    return a;
}
__device__ __forceinline__ void ldsm_x4(uint32_t& r0, uint32_t& r1, uint32_t& r2,
                                        uint32_t& r3, uint32_t addr) {
    asm volatile("ldmatrix.sync.aligned.m8n8.x4.shared.b16 {%0,%1,%2,%3}, [%4];"
                 : "=r"(r0), "=r"(r1), "=r"(r2), "=r"(r3) : "r"(addr));
}
__device__ __forceinline__ void ldsm_x2(uint32_t& r0, uint32_t& r1, uint32_t addr) {
    asm volatile("ldmatrix.sync.aligned.m8n8.x2.shared.b16 {%0,%1}, [%2];"
                 : "=r"(r0), "=r"(r1) : "r"(addr));
}
__device__ __forceinline__ void mma_bf16(float* c, const uint32_t* a, const uint32_t* b) {
    asm volatile(
        "mma.sync.aligned.m16n8k16.row.col.f32.bf16.bf16.f32 "
        "{%0,%1,%2,%3}, {%4,%5,%6,%7}, {%8,%9}, {%0,%1,%2,%3};"
        : "+f"(c[0]), "+f"(c[1]), "+f"(c[2]), "+f"(c[3])
        : "r"(a[0]), "r"(a[1]), "r"(a[2]), "r"(a[3]), "r"(b[0]), "r"(b[1]));
}

#define BKP 72                       // padded row: 64 bf16 + 8 pad (144 B)
#define PLANE (128 * BKP * 2)        // 18432 B per 128x64 smem plane

#define LOAD_PLANES(Ah, Al, Bh, Bl, aRow, bRow, gstride, k0)                          \
    {                                                                                  \
        _Pragma("unroll")                                                              \
        for (int j = 0; j < 4; j++) {                                                  \
            const int c16 = half * 4 + j;                                              \
            const int gofs = (k0) + c16 * 8;                                           \
            const uint32_t so = (uint32_t)(rw * (BKP * 2) + c16 * 16);                 \
            *(uint4*)(dyn + 0 * PLANE + so) = *(const uint4*)&(Ah)[(size_t)(aRow) * (gstride) + gofs]; \
            *(uint4*)(dyn + 1 * PLANE + so) = *(const uint4*)&(Al)[(size_t)(aRow) * (gstride) + gofs]; \
            *(uint4*)(dyn + 2 * PLANE + so) = *(const uint4*)&(Bh)[(size_t)(bRow) * (gstride) + gofs]; \
            *(uint4*)(dyn + 3 * PLANE + so) = *(const uint4*)&(Bl)[(size_t)(bRow) * (gstride) + gofs]; \
        }                                                                              \
    }

#define COMPUTE_CHUNK(sAh, sAl, sBh, sBl)                                              \
    {                                                                                  \
        _Pragma("unroll")                                                              \
        for (int kk = 0; kk < 4; kk++) {                                               \
            uint32_t ah[4][4], al[4][4], bh[4][2], bl[4][2];                           \
            const int a_row = warp_m * 64 + (lane & 15);                               \
            const uint32_t a_cb = (uint32_t)(kk * 32 + (lane >> 4) * 16);              \
            _Pragma("unroll")                                                          \
            for (int fm = 0; fm < 4; fm++) {                                           \
                const uint32_t off = (uint32_t)((a_row + fm * 16) * (BKP * 2)) + a_cb; \
                ldsm_x4(ah[fm][0], ah[fm][1], ah[fm][2], ah[fm][3], (sAh) + off);      \
                ldsm_x4(al[fm][0], al[fm][1], al[fm][2], al[fm][3], (sAl) + off);      \
            }                                                                          \
            const int b_row = warp_n * 32 + (lane & 7);                                \
            const uint32_t b_cb = (uint32_t)(kk * 32 + ((lane >> 3) & 1) * 16);        \
            _Pragma("unroll")                                                          \
            for (int fn = 0; fn < 4; fn++) {                                           \
                const uint32_t off = (uint32_t)((b_row + fn * 8) * (BKP * 2)) + b_cb;  \
                ldsm_x2(bh[fn][0], bh[fn][1], (sBh) + off);                            \
                ldsm_x2(bl[fn][0], bl[fn][1], (sBl) + off);                            \
            }                                                                          \
            _Pragma("unroll")                                                          \
            for (int fm = 0; fm < 4; fm++)                                             \
                _Pragma("unroll")                                                      \
                for (int fn = 0; fn < 4; fn++) {                                       \
                    mma_bf16(acc[fm][fn], ah[fm], bh[fn]);                             \
                    mma_bf16(acc[fm][fn], ah[fm], bl[fn]);                             \
                    mma_bf16(acc[fm][fn], al[fm], bh[fn]);                             \
                }                                                                      \
        }                                                                              \
    }

// ---------------------------------------------------------------------------
// Input conversions
// ---------------------------------------------------------------------------
__global__ __launch_bounds__(256) void k_cvt_x(const float* __restrict__ x) {
    const int idx = blockIdx.x * 256 + threadIdx.x;     // over T*C/4
    const int base = idx * 4;
    float4 v = *(const float4*)&x[base];
    float a[4] = {v.x, v.y, v.z, v.w};
    __nv_bfloat16 h[4], l[4];
#pragma unroll
    for (int i = 0; i < 4; i++) {
        h[i] = __float2bfloat16(a[i]);
        l[i] = __float2bfloat16(a[i] - __bfloat162float(h[i]));
    }
    *(uint2*)&g_x_hi[base] = *(uint2*)h;
    *(uint2*)&g_x_lo[base] = *(uint2*)l;
}

__global__ void k_cvt_w(const float* __restrict__ W) {
    __shared__ float tile[32][33];
    const int c0 = blockIdx.x * 32;   // n block
    const int r0 = blockIdx.y * 32;   // k block
    const int tx = threadIdx.x, ty = threadIdx.y;
#pragma unroll
    for (int yy = ty; yy < 32; yy += 8)
        tile[yy][tx] = W[(size_t)(r0 + yy) * N3 + c0 + tx];
    __syncthreads();
#pragma unroll
    for (int yy = ty; yy < 32; yy += 8) {
        const float v = tile[tx][yy];
        const __nv_bfloat16 h = __float2bfloat16(v);
        const __nv_bfloat16 l = __float2bfloat16(v - __bfloat162float(h));
        g_wT_hi[(size_t)(c0 + yy) * C + r0 + tx] = h;
        g_wT_lo[(size_t)(c0 + yy) * C + r0 + tx] = l;
    }
}

// ---------------------------------------------------------------------------
// Pass 1 (HMMA): qkv = x @ W + b
// ---------------------------------------------------------------------------
__global__ __launch_bounds__(256) void k_qkv_mma(const float* __restrict__ bias) {
    const int bm = blockIdx.y * 128;
    const int bn = blockIdx.x * 128;
    const int tid = threadIdx.x;
    extern __shared__ char dyn[];
    const uint32_t sb = smem_u32(dyn);
    const uint32_t sAh = sb, sAl = sb + PLANE, sBh = sb + 2 * PLANE, sBl = sb + 3 * PLANE;
    const int wid = tid >> 5, lane = tid & 31;
    const int warp_m = wid >> 2, warp_n = wid & 3;
    const int rw = tid >> 1, half = tid & 1;

    float acc[4][4][4];
#pragma unroll
    for (int fm = 0; fm < 4; fm++)
#pragma unroll
        for (int fn = 0; fn < 4; fn++)
#pragma unroll
            for (int e = 0; e < 4; e++) acc[fm][fn][e] = 0.f;

    for (int k0 = 0; k0 < C; k0 += 64) {
        LOAD_PLANES(g_x_hi, g_x_lo, g_wT_hi, g_wT_lo, bm + rw, bn + rw, C, k0);
        __syncthreads();
        COMPUTE_CHUNK(sAh, sAl, sBh, sBl);
        __syncthreads();
    }

    const int er = lane >> 2, ec = (lane & 3) * 2;
#pragma unroll
    for (int fm = 0; fm < 4; fm++)
#pragma unroll
        for (int fn = 0; fn < 4; fn++) {
            const int col = bn + warp_n * 32 + fn * 8 + ec;
            const float b0 = bias[col], b1 = bias[col + 1];
#pragma unroll
            for (int h = 0; h < 2; h++) {
                const int row = bm + warp_m * 64 + fm * 16 + er + h * 8;
                float2 o;
                o.x = acc[fm][fn][h * 2 + 0] + b0;
                o.y = acc[fm][fn][h * 2 + 1] + b1;
                *(float2*)&g_qkv[(size_t)row * N3 + col] = o;
            }
        }
}

// ---------------------------------------------------------------------------
// Split q, k into bf16 hi/lo planes; v -> vT hi/lo
// ---------------------------------------------------------------------------
__global__ __launch_bounds__(256) void k_cvt_qk() {
    const int idx = blockIdx.x * 256 + threadIdx.x;   // over T*NF/4
    const int row = idx >> 6;
    const int c = (idx & 63) * 4;
    float4 q = *(const float4*)&g_qkv[(size_t)row * N3 + c];
    float4 k = *(const float4*)&g_qkv[(size_t)row * N3 + NF + c];
    float qa[4] = {q.x, q.y, q.z, q.w};
    float ka[4] = {k.x, k.y, k.z, k.w};
    __nv_bfloat16 qh[4], ql[4], kh[4], kl[4];
#pragma unroll
    for (int i = 0; i < 4; i++) {
        qh[i] = __float2bfloat16(qa[i]);
        ql[i] = __float2bfloat16(qa[i] - __bfloat162float(qh[i]));
        kh[i] = __float2bfloat16(ka[i]);
        kl[i] = __float2bfloat16(ka[i] - __bfloat162float(kh[i]));
    }
    *(uint2*)&g_q_hi[row * NF + c] = *(uint2*)qh;
    *(uint2*)&g_q_lo[row * NF + c] = *(uint2*)ql;
    *(uint2*)&g_k_hi[row * NF + c] = *(uint2*)kh;
    *(uint2*)&g_k_lo[row * NF + c] = *(uint2*)kl;
}

__global__ void k_cvt_v() {
    __shared__ float tile[32][33];
    const int c0 = blockIdx.x * 32;   // n block (0..NF)
    const int r0 = blockIdx.y * 32;   // j block (0..T)
    const int tx = threadIdx.x, ty = threadIdx.y;
#pragma unroll
    for (int yy = ty; yy < 32; yy += 8)
        tile[yy][tx] = g_qkv[(size_t)(r0 + yy) * N3 + 2 * NF + c0 + tx];
    __syncthreads();
#pragma unroll
    for (int yy = ty; yy < 32; yy += 8) {
        const float v = tile[tx][yy];
        const __nv_bfloat16 h = __float2bfloat16(v);
        const __nv_bfloat16 l = __float2bfloat16(v - __bfloat162float(h));
        g_vT_hi[(size_t)(c0 + yy) * T + r0 + tx] = h;
        g_vT_lo[(size_t)(c0 + yy) * T + r0 + tx] = l;
    }
}

// ---------------------------------------------------------------------------
// Flash attention kernel: CTA = 64 q-rows x one j-chunk of JCH.
// 8 warps: wm = wid&3 (16-row slab), wn = wid>>2 (j/Y column half).
// Per 64-col j-tile: scores HMMA -> online softmax -> p hi/lo to SMEM ->
// p@v HMMA into fp32 Y accumulators. Unnormalized (m, l, Y) to partials.
// ---------------------------------------------------------------------------
#define QSTR 528                     // q/k smem row bytes (264 bf16)
#define VSTR 144                     // vT / p smem row bytes (72 bf16)
#define QPL  (64 * QSTR)             // 33792
#define VPL  (256 * VSTR)            // 36864
#define PPL  (64 * VSTR)             // 9216
#define FLASH_SMEM (4 * QPL + 2 * VPL + 2 * PPL)   // 227328

__global__ __launch_bounds__(256, 1) void k_flash(const int* __restrict__ npadd_p) {
    const int n_padd = *npadd_p;
    const int bm = blockIdx.x * 64;
    const int s = blockIdx.y;

    const int al = (n_padd >> 6) << 6;
    int lo = s * JCH; if (lo < al) lo = al;
    int hi = (s + 1) * JCH; if (hi > bm + 64) hi = bm + 64;
    if (lo >= hi) return;

    extern __shared__ char dyn[];
    char* dQh = dyn;            char* dQl = dyn + QPL;
    char* dKh = dyn + 2 * QPL;  char* dKl = dyn + 3 * QPL;
    char* dVh = dyn + 4 * QPL;  char* dVl = dVh + VPL;
    char* dPh = dVh + 2 * VPL;  char* dPl = dPh + PPL;
    const uint32_t sb = smem_u32(dyn);
    const uint32_t sQh = sb, sQl = sb + QPL;
    const uint32_t sKh = sb + 2 * QPL, sKl = sb + 3 * QPL;
    const uint32_t sVh = sb + 4 * QPL, sVl = sVh + VPL;
    const uint32_t sPh = sVh + 2 * VPL, sPl = sPh + PPL;

    __shared__ float sMax[2][64];
    __shared__ float sSum[2][64];

    const int tid = threadIdx.x;
    const int wid = tid >> 5, lane = tid & 31;
    const int wm = wid & 3, wn = wid >> 2;
    const int er = lane >> 2, ec = (lane & 3) * 2;
    const int r0i = wm * 16 + er;        // local row (and +8)

    // load q slab once (64 x 256, hi+lo)
#pragma unroll
    for (int t = 0; t < 8; t++) {
        const int e = t * 256 + tid;
        const int row = e >> 5, c16 = e & 31;
        *(uint4*)(dQh + row * QSTR + c16 * 16) = *(const uint4*)&g_q_hi[(bm + row) * NF + c16 * 8];
        *(uint4*)(dQl + row * QSTR + c16 * 16) = *(const uint4*)&g_q_lo[(bm + row) * NF + c16 * 8];
    }

    float accY[16][4];
#pragma unroll
    for (int nf = 0; nf < 16; nf++)
#pragma unroll
        for (int e = 0; e < 4; e++) accY[nf][e] = 0.f;
    float m0 = NEGINF, m1 = NEGINF, l0 = 0.f, l1 = 0.f;

    for (int jt = lo; jt < hi; jt += 64) {
        __syncthreads();   // prior tile's MMAs done before overwriting K/V/P
        // load k tile (64x256) and vT tile (256x64), hi+lo
#pragma unroll
        for (int t = 0; t < 8; t++) {
            const int e = t * 256 + tid;
            {
                const int row = e >> 5, c16 = e & 31;
                *(uint4*)(dKh + row * QSTR + c16 * 16) = *(const uint4*)&g_k_hi[(jt + row) * NF + c16 * 8];
                *(uint4*)(dKl + row * QSTR + c16 * 16) = *(const uint4*)&g_k_lo[(jt + row) * NF + c16 * 8];
            }
            {
                const int row = e >> 3, c16 = e & 7;
                *(uint4*)(dVh + row * VSTR + c16 * 16) = *(const uint4*)&g_vT_hi[(size_t)row * T + jt + c16 * 8];
                *(uint4*)(dVl + row * VSTR + c16 * 16) = *(const uint4*)&g_vT_lo[(size_t)row * T + jt + c16 * 8];
            }
        }
        __syncthreads();

        // ---- scores: S (16 x 32 per warp), K=256 ----
        float S[4][4];
#pragma unroll
        for (int fn = 0; fn < 4; fn++)
#pragma unroll
            for (int e = 0; e < 4; e++) S[fn][e] = 0.f;
#pragma unroll
        for (int kk = 0; kk < 16; kk++) {
            uint32_t ah[4], aL[4];
            const int a_row = wm * 16 + (lane & 15);
            const uint32_t a_off = (uint32_t)(a_row * QSTR) + kk * 32 + (lane >> 4) * 16;
            ldsm_x4(ah[0], ah[1], ah[2], ah[3], sQh + a_off);
            ldsm_x4(aL[0], aL[1], aL[2], aL[3], sQl + a_off);
#pragma unroll
            for (int fn = 0; fn < 4; fn++) {
                const int b_row = wn * 32 + fn * 8 + (lane & 7);
                const uint32_t b_off = (uint32_t)(b_row * QSTR) + kk * 32 + ((lane >> 3) & 1) * 16;
                uint32_t bh[2], bL[2];
                ldsm_x2(bh[0], bh[1], sKh + b_off);
                ldsm_x2(bL[0], bL[1], sKl + b_off);
                mma_bf16(S[fn], ah, bh);
                mma_bf16(S[fn], ah, bL);
                mma_bf16(S[fn], aL, bh);
            }
        }

        // ---- scale + mask + tile row-max ----
        const int gi0 = bm + r0i;   // rows gi0, gi0+8
        float tmax0 = NEGINF, tmax1 = NEGINF;
#pragma unroll
        for (int fn = 0; fn < 4; fn++) {
            const int j0 = jt + wn * 32 + fn * 8 + ec;
            S[fn][0] = (j0 <= gi0 && j0 >= n_padd) ? S[fn][0] * SCALE : NEGINF;
            S[fn][1] = (j0 + 1 <= gi0 && j0 + 1 >= n_padd) ? S[fn][1] * SCALE : NEGINF;
            S[fn][2] = (j0 <= gi0 + 8 && j0 >= n_padd) ? S[fn][2] * SCALE : NEGINF;
            S[fn][3] = (j0 + 1 <= gi0 + 8 && j0 + 1 >= n_padd) ? S[fn][3] * SCALE : NEGINF;
            tmax0 = fmaxf(tmax0, fmaxf(S[fn][0], S[fn][1]));
            tmax1 = fmaxf(tmax1, fmaxf(S[fn][2], S[fn][3]));
        }
        tmax0 = fmaxf(tmax0, __shfl_xor_sync(0xffffffffu, tmax0, 1));
        tmax0 = fmaxf(tmax0, __shfl_xor_sync(0xffffffffu, tmax0, 2));
        tmax1 = fmaxf(tmax1, __shfl_xor_sync(0xffffffffu, tmax1, 1));
        tmax1 = fmaxf(tmax1, __shfl_xor_sync(0xffffffffu, tmax1, 2));
        if ((lane & 3) == 0) { sMax[wn][r0i] = tmax0; sMax[wn][r0i + 8] = tmax1; }
        __syncthreads();
        const float rmax0 = fmaxf(sMax[0][r0i], sMax[1][r0i]);
        const float rmax1 = fmaxf(sMax[0][r0i + 8], sMax[1][r0i + 8]);

        const float mn0 = fmaxf(m0, rmax0), mn1 = fmaxf(m1, rmax1);
        const float sc0 = __expf(m0 - mn0), sc1 = __expf(m1 - mn1);

        // ---- p = exp(S - m), row sums, p -> SMEM hi/lo ----
        float ps0 = 0.f, ps1 = 0.f;
#pragma unroll
        for (int fn = 0; fn < 4; fn++) {
            const float p00 = __expf(S[fn][0] - mn0);
            const float p01 = __expf(S[fn][1] - mn0);
            const float p10 = __expf(S[fn][2] - mn1);
            const float p11 = __expf(S[fn][3] - mn1);
            ps0 += p00 + p01;
            ps1 += p10 + p11;
            const __nv_bfloat16 h00 = __float2bfloat16(p00), h01 = __float2bfloat16(p01);
            const __nv_bfloat16 h10 = __float2bfloat16(p10), h11 = __float2bfloat16(p11);
            const __nv_bfloat16 q00 = __float2bfloat16(p00 - __bfloat162float(h00));
            const __nv_bfloat16 q01 = __float2bfloat16(p01 - __bfloat162float(h01));
            const __nv_bfloat16 q10 = __float2bfloat16(p10 - __bfloat162float(h10));
            const __nv_bfloat16 q11 = __float2bfloat16(p11 - __bfloat162float(h11));
            const int pcb = (wn * 32 + fn * 8 + ec) * 2;
            __nv_bfloat16 pk[2];
            pk[0] = h00; pk[1] = h01;
            *(uint32_t*)(dPh + r0i * VSTR + pcb) = *(uint32_t*)pk;
            pk[0] = h10; pk[1] = h11;
            *(uint32_t*)(dPh + (r0i + 8) * VSTR + pcb) = *(uint32_t*)pk;
            pk[0] = q00; pk[1] = q01;
            *(uint32_t*)(dPl + r0i * VSTR + pcb) = *(uint32_t*)pk;
            pk[0] = q10; pk[1] = q11;
            *(uint32_t*)(dPl + (r0i + 8) * VSTR + pcb) = *(uint32_t*)pk;
        }
        ps0 += __shfl_xor_sync(0xffffffffu, ps0, 1);
        ps0 += __shfl_xor_sync(0xffffffffu, ps0, 2);
        ps1 += __shfl_xor_sync(0xffffffffu, ps1, 1);
        ps1 += __shfl_xor_sync(0xffffffffu, ps1, 2);
        if ((lane & 3) == 0) { sSum[wn][r0i] = ps0; sSum[wn][r0i + 8] = ps1; }
        __syncthreads();

        l0 = l0 * sc0 + sSum[0][r0i] + sSum[1][r0i];
        l1 = l1 * sc1 + sSum[0][r0i + 8] + sSum[1][r0i + 8];
        m0 = mn0; m1 = mn1;

        // ---- rescale Y, then Y += p @ v ----
#pragma unroll
        for (int nf = 0; nf < 16; nf++) {
            accY[nf][0] *= sc0; accY[nf][1] *= sc0;
            accY[nf][2] *= sc1; accY[nf][3] *= sc1;
        }
#pragma unroll
        for (int kk = 0; kk < 4; kk++) {
            uint32_t pah[4], paL[4];
            const int a_row = wm * 16 + (lane & 15);
            const uint32_t a_off = (uint32_t)(a_row * VSTR) + kk * 32 + (lane >> 4) * 16;
            ldsm_x4(pah[0], pah[1], pah[2], pah[3], sPh + a_off);
            ldsm_x4(paL[0], paL[1], paL[2], paL[3], sPl + a_off);
#pragma unroll
            for (int nf = 0; nf < 16; nf++) {
                const int b_row = wn * 128 + nf * 8 + (lane & 7);
                const uint32_t b_off = (uint32_t)(b_row * VSTR) + kk * 32 + ((lane >> 3) & 1) * 16;
                uint32_t vh[2], vL[2];
                ldsm_x2(vh[0], vh[1], sVh + b_off);
                ldsm_x2(vL[0], vL[1], sVl + b_off);
                mma_bf16(accY[nf], pah, vh);
                mma_bf16(accY[nf], pah, vL);
                mma_bf16(accY[nf], paL, vh);
            }
        }
    }

    // ---- write partials ----
    float* fy = &g_fy[(size_t)s * T * NF];
#pragma unroll
    for (int nf = 0; nf < 16; nf++) {
        const int col = wn * 128 + nf * 8 + ec;
        const int row0 = bm + r0i, row1 = row0 + 8;
        float2 o0, o1;
        o0.x = accY[nf][0]; o0.y = accY[nf][1];
        o1.x = accY[nf][2]; o1.y = accY[nf][3];
        *(float2*)&fy[(size_t)row0 * NF + col] = o0;
        *(float2*)&fy[(size_t)row1 * NF + col] = o1;
    }
    if (wn == 0 && (lane & 3) == 0) {
        g_fm[s * T + bm + r0i] = m0;
        g_fm[s * T + bm + r0i + 8] = m1;
        g_fl[s * T + bm + r0i] = l0;
        g_fl[s * T + bm + r0i + 8] = l1;
    }
}

// ---------------------------------------------------------------------------
// Combine: y_i = sum_s exp(m_s - M) Y_s / sum_s exp(m_s - M) l_s; zero pads.
// Validity predicate mirrors k_flash exactly.
// ---------------------------------------------------------------------------
__global__ __launch_bounds__(256) void k_combine(const int* __restrict__ npadd_p,
                                                 float* __restrict__ out) {
    const int n_padd = *npadd_p;
    const int idx = blockIdx.x * 256 + threadIdx.x;
    const int i = idx >> 6;
    const int c4 = (idx & 63) * 4;

    float4 o = make_float4(0.f, 0.f, 0.f, 0.f);
    if (i >= n_padd) {
        const int bm = (i >> 6) << 6;
        const int al = (n_padd >> 6) << 6;
        float M = NEGINF;
#pragma unroll
        for (int s = 0; s < JSPLIT; s++) {
            int lo = s * JCH; if (lo < al) lo = al;
            int hi = (s + 1) * JCH; if (hi > bm + 64) hi = bm + 64;
            if (lo < hi) M = fmaxf(M, g_fm[s * T + i]);
        }
        float den = 0.f;
        float4 acc = make_float4(0.f, 0.f, 0.f, 0.f);
#pragma unroll
        for (int s = 0; s < JSPLIT; s++) {
            int lo = s * JCH; if (lo < al) lo = al;
            int hi = (s + 1) * JCH; if (hi > bm + 64) hi = bm + 64;
            if (lo < hi) {
                const float w = __expf(g_fm[s * T + i] - M);
                den += w * g_fl[s * T + i];
                float4 y = *(const float4*)&g_fy[((size_t)s * T + i) * NF + c4];
                acc.x += w * y.x; acc.y += w * y.y;
                acc.z += w * y.z; acc.w += w * y.w;
            }
        }
        const float inv = 1.f / den;
        o.x = acc.x * inv; o.y = acc.y * inv;
        o.z = acc.z * inv; o.w = acc.w * inv;
    }
    *(float4*)&out[(size_t)i * NF + c4] = o;
}

// ---------------------------------------------------------------------------
extern "C" void kernel_launch(void* const* d_in, const int* in_sizes, int n_in,
                              void* d_out, int out_size) {
    const float* x = (const float*)d_in[0];
    const float* W = (const float*)d_in[1];
    const float* b = (const float*)d_in[2];
    const int* n_padd = (const int*)d_in[3];
    float* out = (float*)d_out;

    cudaFuncSetAttribute(k_qkv_mma, cudaFuncAttributeMaxDynamicSharedMemorySize, 4 * PLANE);
    cudaFuncSetAttribute(k_flash, cudaFuncAttributeMaxDynamicSharedMemorySize, FLASH_SMEM);

    k_cvt_x<<<(T * C / 4) / 256, 256>>>(x);
    k_cvt_w<<<dim3(N3 / 32, C / 32), dim3(32, 8)>>>(W);
    k_qkv_mma<<<dim3(N3 / 128, T / 128), 256, 4 * PLANE>>>(b);
    k_cvt_qk<<<(T * NF / 4) / 256, 256>>>();
    k_cvt_v<<<dim3(NF / 32, T / 32), dim3(32, 8)>>>();
    k_flash<<<dim3(T / 64, JSPLIT), 256, FLASH_SMEM>>>(n_padd);
    k_combine<<<(T * NF / 4) / 256, 256>>>(n_padd, out);
}

// round 10
// speedup vs baseline: 2.8985x; 1.1030x over previous
#include <cuda_runtime.h>
#include <cuda_bf16.h>
#include <cstdint>

#define T      4096
#define C      1024
#define NF     256
#define N3     768          // 3 * NF
#define SCALE  0.0625f      // 1/sqrt(256)
#define NEGINF -1e30f
#define JSPLIT 8
#define JCH    (T / JSPLIT) // 512

// Scratch (alloc-free rule: __device__ globals)
__device__ float g_qkv[T * N3];                        // 12 MB
__device__ __nv_bfloat16 g_x_hi[T * C];                // 8 MB each
__device__ __nv_bfloat16 g_x_lo[T * C];
__device__ __nv_bfloat16 g_wT_hi[N3 * C];              // 1.5 MB each, [n][k]
__device__ __nv_bfloat16 g_wT_lo[N3 * C];
__device__ __nv_bfloat16 g_q_hi[T * NF];               // 2 MB each
__device__ __nv_bfloat16 g_q_lo[T * NF];
__device__ __nv_bfloat16 g_k_hi[T * NF];
__device__ __nv_bfloat16 g_k_lo[T * NF];
__device__ __nv_bfloat16 g_vT_hi[NF * T];              // 2 MB each, [n][k]
__device__ __nv_bfloat16 g_vT_lo[NF * T];
__device__ float g_fy[(size_t)JSPLIT * T * NF];        // 32 MB unnormalized Y partials
__device__ float g_fm[JSPLIT * T];                     // row max per chunk
__device__ float g_fl[JSPLIT * T];                     // row sum per chunk

__device__ __forceinline__ uint32_t smem_u32(const void* p) {
    uint32_t a;
    asm("{ .reg .u64 t; cvta.to.shared.u64 t, %1; cvt.u32.u64 %0, t; }" : "=r"(a) : "l"(p));
    return a;
}
__device__ __forceinline__ void ldsm_x4(uint32_t& r0, uint32_t& r1, uint32_t& r2,
                                        uint32_t& r3, uint32_t addr) {
    asm volatile("ldmatrix.sync.aligned.m8n8.x4.shared.b16 {%0,%1,%2,%3}, [%4];"
                 : "=r"(r0), "=r"(r1), "=r"(r2), "=r"(r3) : "r"(addr));
}
__device__ __forceinline__ void mma_bf16(float* c, const uint32_t* a, const uint32_t* b) {
    asm volatile(
        "mma.sync.aligned.m16n8k16.row.col.f32.bf16.bf16.f32 "
        "{%0,%1,%2,%3}, {%4,%5,%6,%7}, {%8,%9}, {%0,%1,%2,%3};"
        : "+f"(c[0]), "+f"(c[1]), "+f"(c[2]), "+f"(c[3])
        : "r"(a[0]), "r"(a[1]), "r"(a[2]), "r"(a[3]), "r"(b[0]), "r"(b[1]));
}

#define BKP 72                       // padded row: 64 bf16 + 8 pad (144 B)
#define PLANE (128 * BKP * 2)        // 18432 B per 128x64 smem plane

#define LOAD_PLANES(Ah, Al, Bh, Bl, aRow, bRow, gstride, k0)                          \
    {                                                                                  \
        _Pragma("unroll")                                                              \
        for (int j = 0; j < 4; j++) {                                                  \
            const int c16 = half * 4 + j;                                              \
            const int gofs = (k0) + c16 * 8;                                           \
            const uint32_t so = (uint32_t)(rw * (BKP * 2) + c16 * 16);                 \
            *(uint4*)(dyn + 0 * PLANE + so) = *(const uint4*)&(Ah)[(size_t)(aRow) * (gstride) + gofs]; \
            *(uint4*)(dyn + 1 * PLANE + so) = *(const uint4*)&(Al)[(size_t)(aRow) * (gstride) + gofs]; \
            *(uint4*)(dyn + 2 * PLANE + so) = *(const uint4*)&(Bh)[(size_t)(bRow) * (gstride) + gofs]; \
            *(uint4*)(dyn + 3 * PLANE + so) = *(const uint4*)&(Bl)[(size_t)(bRow) * (gstride) + gofs]; \
        }                                                                              \
    }

// B fragments loaded as PAIRS via ldsm_x4 (two fn frags, both k16-halves).
#define COMPUTE_CHUNK(sAh, sAl, sBh, sBl)                                              \
    {                                                                                  \
        _Pragma("unroll")                                                              \
        for (int kk = 0; kk < 4; kk++) {                                               \
            uint32_t ah[4][4], al[4][4], bh[4][2], bl[4][2];                           \
            const int a_row = warp_m * 64 + (lane & 15);                               \
            const uint32_t a_cb = (uint32_t)(kk * 32 + (lane >> 4) * 16);              \
            _Pragma("unroll")                                                          \
            for (int fm = 0; fm < 4; fm++) {                                           \
                const uint32_t off = (uint32_t)((a_row + fm * 16) * (BKP * 2)) + a_cb; \
                ldsm_x4(ah[fm][0], ah[fm][1], ah[fm][2], ah[fm][3], (sAh) + off);      \
                ldsm_x4(al[fm][0], al[fm][1], al[fm][2], al[fm][3], (sAl) + off);      \
            }                                                                          \
            const int b_base = warp_n * 32 + ((lane >> 4) & 1) * 8 + (lane & 7);       \
            const uint32_t b_cb = (uint32_t)(kk * 32 + ((lane >> 3) & 1) * 16);        \
            _Pragma("unroll")                                                          \
            for (int fp = 0; fp < 2; fp++) {                                           \
                const uint32_t off = (uint32_t)((b_base + fp * 16) * (BKP * 2)) + b_cb;\
                ldsm_x4(bh[2 * fp][0], bh[2 * fp][1], bh[2 * fp + 1][0],               \
                        bh[2 * fp + 1][1], (sBh) + off);                               \
                ldsm_x4(bl[2 * fp][0], bl[2 * fp][1], bl[2 * fp + 1][0],               \
                        bl[2 * fp + 1][1], (sBl) + off);                               \
            }                                                                          \
            _Pragma("unroll")                                                          \
            for (int fm = 0; fm < 4; fm++)                                             \
                _Pragma("unroll")                                                      \
                for (int fn = 0; fn < 4; fn++) {                                       \
                    mma_bf16(acc[fm][fn], ah[fm], bh[fn]);                             \
                    mma_bf16(acc[fm][fn], ah[fm], bl[fn]);                             \
                    mma_bf16(acc[fm][fn], al[fm], bh[fn]);                             \
                }                                                                      \
        }                                                                              \
    }

// ---------------------------------------------------------------------------
// Input conversions
// ---------------------------------------------------------------------------
__global__ __launch_bounds__(256) void k_cvt_x(const float* __restrict__ x) {
    const int idx = blockIdx.x * 256 + threadIdx.x;     // over T*C/4
    const int base = idx * 4;
    float4 v = *(const float4*)&x[base];
    float a[4] = {v.x, v.y, v.z, v.w};
    __nv_bfloat16 h[4], l[4];
#pragma unroll
    for (int i = 0; i < 4; i++) {
        h[i] = __float2bfloat16(a[i]);
        l[i] = __float2bfloat16(a[i] - __bfloat162float(h[i]));
    }
    *(uint2*)&g_x_hi[base] = *(uint2*)h;
    *(uint2*)&g_x_lo[base] = *(uint2*)l;
}

__global__ void k_cvt_w(const float* __restrict__ W) {
    __shared__ float tile[32][33];
    const int c0 = blockIdx.x * 32;   // n block
    const int r0 = blockIdx.y * 32;   // k block
    const int tx = threadIdx.x, ty = threadIdx.y;
#pragma unroll
    for (int yy = ty; yy < 32; yy += 8)
        tile[yy][tx] = W[(size_t)(r0 + yy) * N3 + c0 + tx];
    __syncthreads();
#pragma unroll
    for (int yy = ty; yy < 32; yy += 8) {
        const float v = tile[tx][yy];
        const __nv_bfloat16 h = __float2bfloat16(v);
        const __nv_bfloat16 l = __float2bfloat16(v - __bfloat162float(h));
        g_wT_hi[(size_t)(c0 + yy) * C + r0 + tx] = h;
        g_wT_lo[(size_t)(c0 + yy) * C + r0 + tx] = l;
    }
}

// ---------------------------------------------------------------------------
// Pass 1 (HMMA): qkv = x @ W + b
// ---------------------------------------------------------------------------
__global__ __launch_bounds__(256) void k_qkv_mma(const float* __restrict__ bias) {
    const int bm = blockIdx.y * 128;
    const int bn = blockIdx.x * 128;
    const int tid = threadIdx.x;
    extern __shared__ char dyn[];
    const uint32_t sb = smem_u32(dyn);
    const uint32_t sAh = sb, sAl = sb + PLANE, sBh = sb + 2 * PLANE, sBl = sb + 3 * PLANE;
    const int wid = tid >> 5, lane = tid & 31;
    const int warp_m = wid >> 2, warp_n = wid & 3;
    const int rw = tid >> 1, half = tid & 1;

    float acc[4][4][4];
#pragma unroll
    for (int fm = 0; fm < 4; fm++)
#pragma unroll
        for (int fn = 0; fn < 4; fn++)
#pragma unroll
            for (int e = 0; e < 4; e++) acc[fm][fn][e] = 0.f;

    for (int k0 = 0; k0 < C; k0 += 64) {
        LOAD_PLANES(g_x_hi, g_x_lo, g_wT_hi, g_wT_lo, bm + rw, bn + rw, C, k0);
        __syncthreads();
        COMPUTE_CHUNK(sAh, sAl, sBh, sBl);
        __syncthreads();
    }

    const int er = lane >> 2, ec = (lane & 3) * 2;
#pragma unroll
    for (int fm = 0; fm < 4; fm++)
#pragma unroll
        for (int fn = 0; fn < 4; fn++) {
            const int col = bn + warp_n * 32 + fn * 8 + ec;
            const float b0 = bias[col], b1 = bias[col + 1];
#pragma unroll
            for (int h = 0; h < 2; h++) {
                const int row = bm + warp_m * 64 + fm * 16 + er + h * 8;
                float2 o;
                o.x = acc[fm][fn][h * 2 + 0] + b0;
                o.y = acc[fm][fn][h * 2 + 1] + b1;
                *(float2*)&g_qkv[(size_t)row * N3 + col] = o;
            }
        }
}

// ---------------------------------------------------------------------------
// Split q, k into bf16 hi/lo planes; v -> vT hi/lo
// ---------------------------------------------------------------------------
__global__ __launch_bounds__(256) void k_cvt_qk() {
    const int idx = blockIdx.x * 256 + threadIdx.x;   // over T*NF/4
    const int row = idx >> 6;
    const int c = (idx & 63) * 4;
    float4 q = *(const float4*)&g_qkv[(size_t)row * N3 + c];
    float4 k = *(const float4*)&g_qkv[(size_t)row * N3 + NF + c];
    float qa[4] = {q.x, q.y, q.z, q.w};
    float ka[4] = {k.x, k.y, k.z, k.w};
    __nv_bfloat16 qh[4], ql[4], kh[4], kl[4];
#pragma unroll
    for (int i = 0; i < 4; i++) {
        qh[i] = __float2bfloat16(qa[i]);
        ql[i] = __float2bfloat16(qa[i] - __bfloat162float(qh[i]));
        kh[i] = __float2bfloat16(ka[i]);
        kl[i] = __float2bfloat16(ka[i] - __bfloat162float(kh[i]));
    }
    *(uint2*)&g_q_hi[row * NF + c] = *(uint2*)qh;
    *(uint2*)&g_q_lo[row * NF + c] = *(uint2*)ql;
    *(uint2*)&g_k_hi[row * NF + c] = *(uint2*)kh;
    *(uint2*)&g_k_lo[row * NF + c] = *(uint2*)kl;
}

__global__ void k_cvt_v() {
    __shared__ float tile[32][33];
    const int c0 = blockIdx.x * 32;   // n block (0..NF)
    const int r0 = blockIdx.y * 32;   // j block (0..T)
    const int tx = threadIdx.x, ty = threadIdx.y;
#pragma unroll
    for (int yy = ty; yy < 32; yy += 8)
        tile[yy][tx] = g_qkv[(size_t)(r0 + yy) * N3 + 2 * NF + c0 + tx];
    __syncthreads();
#pragma unroll
    for (int yy = ty; yy < 32; yy += 8) {
        const float v = tile[tx][yy];
        const __nv_bfloat16 h = __float2bfloat16(v);
        const __nv_bfloat16 l = __float2bfloat16(v - __bfloat162float(h));
        g_vT_hi[(size_t)(c0 + yy) * T + r0 + tx] = h;
        g_vT_lo[(size_t)(c0 + yy) * T + r0 + tx] = l;
    }
}

// ---------------------------------------------------------------------------
// Flash attention kernel: CTA = 64 q-rows x one j-chunk of JCH (512).
// ---------------------------------------------------------------------------
#define QSTR 528                     // q/k smem row bytes (264 bf16)
#define VSTR 144                     // vT / p smem row bytes (72 bf16)
#define QPL  (64 * QSTR)             // 33792
#define VPL  (256 * VSTR)            // 36864
#define PPL  (64 * VSTR)             // 9216
#define FLASH_SMEM (4 * QPL + 2 * VPL + 2 * PPL)   // 227328

__global__ __launch_bounds__(256, 1) void k_flash(const int* __restrict__ npadd_p) {
    const int n_padd = *npadd_p;
    const int bm = blockIdx.x * 64;
    const int s = blockIdx.y;

    const int al = (n_padd >> 6) << 6;
    int lo = s * JCH; if (lo < al) lo = al;
    int hi = (s + 1) * JCH; if (hi > bm + 64) hi = bm + 64;
    if (lo >= hi) return;

    extern __shared__ char dyn[];
    char* dQh = dyn;            char* dQl = dyn + QPL;
    char* dKh = dyn + 2 * QPL;  char* dKl = dyn + 3 * QPL;
    char* dVh = dyn + 4 * QPL;  char* dVl = dVh + VPL;
    char* dPh = dVh + 2 * VPL;  char* dPl = dPh + PPL;
    const uint32_t sb = smem_u32(dyn);
    const uint32_t sQh = sb, sQl = sb + QPL;
    const uint32_t sKh = sb + 2 * QPL, sKl = sb + 3 * QPL;
    const uint32_t sVh = sb + 4 * QPL, sVl = sVh + VPL;
    const uint32_t sPh = sVh + 2 * VPL, sPl = sPh + PPL;

    __shared__ float sMax[2][64];
    __shared__ float sSum[2][64];

    const int tid = threadIdx.x;
    const int wid = tid >> 5, lane = tid & 31;
    const int wm = wid & 3, wn = wid >> 2;
    const int er = lane >> 2, ec = (lane & 3) * 2;
    const int r0i = wm * 16 + er;        // local row (and +8)

    // load q slab once (64 x 256, hi+lo)
#pragma unroll
    for (int t = 0; t < 8; t++) {
        const int e = t * 256 + tid;
        const int row = e >> 5, c16 = e & 31;
        *(uint4*)(dQh + row * QSTR + c16 * 16) = *(const uint4*)&g_q_hi[(bm + row) * NF + c16 * 8];
        *(uint4*)(dQl + row * QSTR + c16 * 16) = *(const uint4*)&g_q_lo[(bm + row) * NF + c16 * 8];
    }

    float accY[16][4];
#pragma unroll
    for (int nf = 0; nf < 16; nf++)
#pragma unroll
        for (int e = 0; e < 4; e++) accY[nf][e] = 0.f;
    float m0 = NEGINF, m1 = NEGINF, l0 = 0.f, l1 = 0.f;

    for (int jt = lo; jt < hi; jt += 64) {
        __syncthreads();   // prior tile's MMAs done before overwriting K/V/P
#pragma unroll
        for (int t = 0; t < 8; t++) {
            const int e = t * 256 + tid;
            {
                const int row = e >> 5, c16 = e & 31;
                *(uint4*)(dKh + row * QSTR + c16 * 16) = *(const uint4*)&g_k_hi[(jt + row) * NF + c16 * 8];
                *(uint4*)(dKl + row * QSTR + c16 * 16) = *(const uint4*)&g_k_lo[(jt + row) * NF + c16 * 8];
            }
            {
                const int row = e >> 3, c16 = e & 7;
                *(uint4*)(dVh + row * VSTR + c16 * 16) = *(const uint4*)&g_vT_hi[(size_t)row * T + jt + c16 * 8];
                *(uint4*)(dVl + row * VSTR + c16 * 16) = *(const uint4*)&g_vT_lo[(size_t)row * T + jt + c16 * 8];
            }
        }
        __syncthreads();

        // ---- scores: S (16 x 32 per warp), K=256 ----
        float S[4][4];
#pragma unroll
        for (int fn = 0; fn < 4; fn++)
#pragma unroll
            for (int e = 0; e < 4; e++) S[fn][e] = 0.f;
#pragma unroll
        for (int kk = 0; kk < 16; kk++) {
            uint32_t ah[4], aL[4], bh[4][2], bL[4][2];
            const int a_row = wm * 16 + (lane & 15);
            const uint32_t a_off = (uint32_t)(a_row * QSTR) + kk * 32 + (lane >> 4) * 16;
            ldsm_x4(ah[0], ah[1], ah[2], ah[3], sQh + a_off);
            ldsm_x4(aL[0], aL[1], aL[2], aL[3], sQl + a_off);
            const int b_base = wn * 32 + ((lane >> 4) & 1) * 8 + (lane & 7);
            const uint32_t b_cb = (uint32_t)(kk * 32 + ((lane >> 3) & 1) * 16);
#pragma unroll
            for (int fp = 0; fp < 2; fp++) {
                const uint32_t off = (uint32_t)((b_base + fp * 16) * QSTR) + b_cb;
                ldsm_x4(bh[2 * fp][0], bh[2 * fp][1], bh[2 * fp + 1][0], bh[2 * fp + 1][1], sKh + off);
                ldsm_x4(bL[2 * fp][0], bL[2 * fp][1], bL[2 * fp + 1][0], bL[2 * fp + 1][1], sKl + off);
            }
#pragma unroll
            for (int fn = 0; fn < 4; fn++) {
                mma_bf16(S[fn], ah, bh[fn]);
                mma_bf16(S[fn], ah, bL[fn]);
                mma_bf16(S[fn], aL, bh[fn]);
            }
        }

        // ---- scale + mask + tile row-max ----
        const int gi0 = bm + r0i;   // rows gi0, gi0+8
        float tmax0 = NEGINF, tmax1 = NEGINF;
#pragma unroll
        for (int fn = 0; fn < 4; fn++) {
            const int j0 = jt + wn * 32 + fn * 8 + ec;
            S[fn][0] = (j0 <= gi0 && j0 >= n_padd) ? S[fn][0] * SCALE : NEGINF;
            S[fn][1] = (j0 + 1 <= gi0 && j0 + 1 >= n_padd) ? S[fn][1] * SCALE : NEGINF;
            S[fn][2] = (j0 <= gi0 + 8 && j0 >= n_padd) ? S[fn][2] * SCALE : NEGINF;
            S[fn][3] = (j0 + 1 <= gi0 + 8 && j0 + 1 >= n_padd) ? S[fn][3] * SCALE : NEGINF;
            tmax0 = fmaxf(tmax0, fmaxf(S[fn][0], S[fn][1]));
            tmax1 = fmaxf(tmax1, fmaxf(S[fn][2], S[fn][3]));
        }
        tmax0 = fmaxf(tmax0, __shfl_xor_sync(0xffffffffu, tmax0, 1));
        tmax0 = fmaxf(tmax0, __shfl_xor_sync(0xffffffffu, tmax0, 2));
        tmax1 = fmaxf(tmax1, __shfl_xor_sync(0xffffffffu, tmax1, 1));
        tmax1 = fmaxf(tmax1, __shfl_xor_sync(0xffffffffu, tmax1, 2));
        if ((lane & 3) == 0) { sMax[wn][r0i] = tmax0; sMax[wn][r0i + 8] = tmax1; }
        __syncthreads();
        const float rmax0 = fmaxf(sMax[0][r0i], sMax[1][r0i]);
        const float rmax1 = fmaxf(sMax[0][r0i + 8], sMax[1][r0i + 8]);

        const float mn0 = fmaxf(m0, rmax0), mn1 = fmaxf(m1, rmax1);
        const float sc0 = __expf(m0 - mn0), sc1 = __expf(m1 - mn1);

        // ---- p = exp(S - m), row sums, p -> SMEM hi/lo ----
        float ps0 = 0.f, ps1 = 0.f;
#pragma unroll
        for (int fn = 0; fn < 4; fn++) {
            const float p00 = __expf(S[fn][0] - mn0);
            const float p01 = __expf(S[fn][1] - mn0);
            const float p10 = __expf(S[fn][2] - mn1);
            const float p11 = __expf(S[fn][3] - mn1);
            ps0 += p00 + p01;
            ps1 += p10 + p11;
            const __nv_bfloat16 h00 = __float2bfloat16(p00), h01 = __float2bfloat16(p01);
            const __nv_bfloat16 h10 = __float2bfloat16(p10), h11 = __float2bfloat16(p11);
            const __nv_bfloat16 q00 = __float2bfloat16(p00 - __bfloat162float(h00));
            const __nv_bfloat16 q01 = __float2bfloat16(p01 - __bfloat162float(h01));
            const __nv_bfloat16 q10 = __float2bfloat16(p10 - __bfloat162float(h10));
            const __nv_bfloat16 q11 = __float2bfloat16(p11 - __bfloat162float(h11));
            const int pcb = (wn * 32 + fn * 8 + ec) * 2;
            __nv_bfloat16 pk[2];
            pk[0] = h00; pk[1] = h01;
            *(uint32_t*)(dPh + r0i * VSTR + pcb) = *(uint32_t*)pk;
            pk[0] = h10; pk[1] = h11;
            *(uint32_t*)(dPh + (r0i + 8) * VSTR + pcb) = *(uint32_t*)pk;
            pk[0] = q00; pk[1] = q01;
            *(uint32_t*)(dPl + r0i * VSTR + pcb) = *(uint32_t*)pk;
            pk[0] = q10; pk[1] = q11;
            *(uint32_t*)(dPl + (r0i + 8) * VSTR + pcb) = *(uint32_t*)pk;
        }
        ps0 += __shfl_xor_sync(0xffffffffu, ps0, 1);
        ps0 += __shfl_xor_sync(0xffffffffu, ps0, 2);
        ps1 += __shfl_xor_sync(0xffffffffu, ps1, 1);
        ps1 += __shfl_xor_sync(0xffffffffu, ps1, 2);
        if ((lane & 3) == 0) { sSum[wn][r0i] = ps0; sSum[wn][r0i + 8] = ps1; }
        __syncthreads();

        l0 = l0 * sc0 + sSum[0][r0i] + sSum[1][r0i];
        l1 = l1 * sc1 + sSum[0][r0i + 8] + sSum[1][r0i + 8];
        m0 = mn0; m1 = mn1;

        // ---- rescale Y, then Y += p @ v ----
#pragma unroll
        for (int nf = 0; nf < 16; nf++) {
            accY[nf][0] *= sc0; accY[nf][1] *= sc0;
            accY[nf][2] *= sc1; accY[nf][3] *= sc1;
        }
#pragma unroll
        for (int kk = 0; kk < 4; kk++) {
            uint32_t pah[4], paL[4];
            const int a_row = wm * 16 + (lane & 15);
            const uint32_t a_off = (uint32_t)(a_row * VSTR) + kk * 32 + (lane >> 4) * 16;
            ldsm_x4(pah[0], pah[1], pah[2], pah[3], sPh + a_off);
            ldsm_x4(paL[0], paL[1], paL[2], paL[3], sPl + a_off);
            const int b_base = wn * 128 + ((lane >> 4) & 1) * 8 + (lane & 7);
            const uint32_t b_cb = (uint32_t)(kk * 32 + ((lane >> 3) & 1) * 16);
#pragma unroll
            for (int np = 0; np < 8; np++) {
                const uint32_t off = (uint32_t)((b_base + np * 16) * VSTR) + b_cb;
                uint32_t vh[4], vL[4];
                ldsm_x4(vh[0], vh[1], vh[2], vh[3], sVh + off);
                ldsm_x4(vL[0], vL[1], vL[2], vL[3], sVl + off);
                mma_bf16(accY[2 * np], pah, &vh[0]);
                mma_bf16(accY[2 * np], pah, &vL[0]);
                mma_bf16(accY[2 * np], paL, &vh[0]);
                mma_bf16(accY[2 * np + 1], pah, &vh[2]);
                mma_bf16(accY[2 * np + 1], pah, &vL[2]);
                mma_bf16(accY[2 * np + 1], paL, &vh[2]);
            }
        }
    }

    // ---- write partials ----
    float* fy = &g_fy[(size_t)s * T * NF];
#pragma unroll
    for (int nf = 0; nf < 16; nf++) {
        const int col = wn * 128 + nf * 8 + ec;
        const int row0 = bm + r0i, row1 = row0 + 8;
        float2 o0, o1;
        o0.x = accY[nf][0]; o0.y = accY[nf][1];
        o1.x = accY[nf][2]; o1.y = accY[nf][3];
        *(float2*)&fy[(size_t)row0 * NF + col] = o0;
        *(float2*)&fy[(size_t)row1 * NF + col] = o1;
    }
    if (wn == 0 && (lane & 3) == 0) {
        g_fm[s * T + bm + r0i] = m0;
        g_fm[s * T + bm + r0i + 8] = m1;
        g_fl[s * T + bm + r0i] = l0;
        g_fl[s * T + bm + r0i + 8] = l1;
    }
}

// ---------------------------------------------------------------------------
// Combine: y_i = sum_s exp(m_s - M) Y_s / sum_s exp(m_s - M) l_s; zero pads.
// ---------------------------------------------------------------------------
__global__ __launch_bounds__(256) void k_combine(const int* __restrict__ npadd_p,
                                                 float* __restrict__ out) {
    const int n_padd = *npadd_p;
    const int idx = blockIdx.x * 256 + threadIdx.x;
    const int i = idx >> 6;
    const int c4 = (idx & 63) * 4;

    float4 o = make_float4(0.f, 0.f, 0.f, 0.f);
    if (i >= n_padd) {
        const int bm = (i >> 6) << 6;
        const int al = (n_padd >> 6) << 6;
        float M = NEGINF;
#pragma unroll
        for (int s = 0; s < JSPLIT; s++) {
            int lo = s * JCH; if (lo < al) lo = al;
            int hi = (s + 1) * JCH; if (hi > bm + 64) hi = bm + 64;
            if (lo < hi) M = fmaxf(M, g_fm[s * T + i]);
        }
        float den = 0.f;
        float4 acc = make_float4(0.f, 0.f, 0.f, 0.f);
#pragma unroll
        for (int s = 0; s < JSPLIT; s++) {
            int lo = s * JCH; if (lo < al) lo = al;
            int hi = (s + 1) * JCH; if (hi > bm + 64) hi = bm + 64;
            if (lo < hi) {
                const float w = __expf(g_fm[s * T + i] - M);
                den += w * g_fl[s * T + i];
                float4 y = *(const float4*)&g_fy[((size_t)s * T + i) * NF + c4];
                acc.x += w * y.x; acc.y += w * y.y;
                acc.z += w * y.z; acc.w += w * y.w;
            }
        }
        const float inv = 1.f / den;
        o.x = acc.x * inv; o.y = acc.y * inv;
        o.z = acc.z * inv; o.w = acc.w * inv;
    }
    *(float4*)&out[(size_t)i * NF + c4] = o;
}

// ---------------------------------------------------------------------------
extern "C" void kernel_launch(void* const* d_in, const int* in_sizes, int n_in,
                              void* d_out, int out_size) {
    const float* x = (const float*)d_in[0];
    const float* W = (const float*)d_in[1];
    const float* b = (const float*)d_in[2];
    const int* n_padd = (const int*)d_in[3];
    float* out = (float*)d_out;

    cudaFuncSetAttribute(k_qkv_mma, cudaFuncAttributeMaxDynamicSharedMemorySize, 4 * PLANE);
    cudaFuncSetAttribute(k_flash, cudaFuncAttributeMaxDynamicSharedMemorySize, FLASH_SMEM);

    k_cvt_x<<<(T * C / 4) / 256, 256>>>(x);
    k_cvt_w<<<dim3(N3 / 32, C / 32), dim3(32, 8)>>>(W);
    k_qkv_mma<<<dim3(N3 / 128, T / 128), 256, 4 * PLANE>>>(b);
    k_cvt_qk<<<(T * NF / 4) / 256, 256>>>();
    k_cvt_v<<<dim3(NF / 32, T / 32), dim3(32, 8)>>>();
    k_flash<<<dim3(T / 64, JSPLIT), 256, FLASH_SMEM>>>(n_padd);
    k_combine<<<(T * NF / 4) / 256, 256>>>(n_padd, out);
}